// round 8
// baseline (speedup 1.0000x reference)
#include <cuda_runtime.h>
#include <cuda_bf16.h>
#include <cstdint>
#include <math.h>

#define B_   4
#define T_   256
#define V_   1024
#define S_   64
#define DIM_ 1024
#define CV_  256
#define SPLITS 4
#define SK_  (DIM_ / SPLITS)

// ---------------------------------------------------------------------------
// Scratch
// ---------------------------------------------------------------------------
__device__ __nv_bfloat16 g_visb[B_ * V_ * CV_];   // vision bf16
__device__ __nv_bfloat16 g_xb  [B_ * T_ * DIM_]; // x bf16
__device__ __nv_bfloat16 g_Wub [CV_ * DIM_];
__device__ __nv_bfloat16 g_Wkb [DIM_ * DIM_];
__device__ __nv_bfloat16 g_Wvb [DIM_ * DIM_];
__device__ __nv_bfloat16 g_Wuk [CV_ * DIM_];      // Wu@Wk  [c, n] row-major
__device__ __nv_bfloat16 g_Wuv [CV_ * DIM_];      // Wu@Wv
__device__ float         g_part[2 * SPLITS][CV_ * DIM_];
__device__ float         g_buk [DIM_];
__device__ float         g_buv [DIM_];
__device__ float         g_bdot[B_ * T_];         // buk . x[t]
__device__ __nv_bfloat16 g_xq  [B_ * T_ * CV_];   // x @ Wuk^T
__device__ float         g_logitD[B_ * T_ * V_];  // dense logits (4MB)
__device__ __nv_bfloat16 g_w   [B_ * T_ * V_];    // softmax weights (2MB)
__device__ float         g_wsum[B_ * T_];
__device__ __nv_bfloat16 g_agg [B_ * T_ * CV_];   // w @ vision
__device__ float2        g_ms  [B_ * T_];         // per-(b,t) masked (max,sumexp)

// ---------------------------------------------------------------------------
// helpers
// ---------------------------------------------------------------------------
__device__ __forceinline__ uint32_t smem_u32(const void* p) {
    uint32_t a;
    asm("{ .reg .u64 t; cvta.to.shared.u64 t, %1; cvt.u32.u64 %0, t; }"
        : "=r"(a) : "l"(p));
    return a;
}
__device__ __forceinline__ void cp_async16(uint32_t dst, const void* src) {
    asm volatile("cp.async.cg.shared.global [%0], [%1], 16;" :: "r"(dst), "l"(src));
}
#define CP_COMMIT() asm volatile("cp.async.commit_group;" ::: "memory")
#define CP_WAIT(n)  asm volatile("cp.async.wait_group %0;" :: "n"(n) : "memory")

__device__ __forceinline__ void ldmatrix_x4(uint32_t* r, uint32_t addr) {
    asm volatile("ldmatrix.sync.aligned.m8n8.x4.shared.b16 {%0,%1,%2,%3}, [%4];"
                 : "=r"(r[0]), "=r"(r[1]), "=r"(r[2]), "=r"(r[3]) : "r"(addr));
}
__device__ __forceinline__ void ldmatrix_x4_trans(uint32_t* r, uint32_t addr) {
    asm volatile("ldmatrix.sync.aligned.m8n8.x4.trans.shared.b16 {%0,%1,%2,%3}, [%4];"
                 : "=r"(r[0]), "=r"(r[1]), "=r"(r[2]), "=r"(r[3]) : "r"(addr));
}
__device__ __forceinline__ void mma16816(float* d, const uint32_t* a, const uint32_t* b) {
    asm volatile(
        "mma.sync.aligned.m16n8k16.row.col.f32.bf16.bf16.f32 "
        "{%0,%1,%2,%3},{%4,%5,%6,%7},{%8,%9},{%0,%1,%2,%3};"
        : "+f"(d[0]), "+f"(d[1]), "+f"(d[2]), "+f"(d[3])
        : "r"(a[0]), "r"(a[1]), "r"(a[2]), "r"(a[3]), "r"(b[0]), "r"(b[1]));
}

#define APAD 8
#define BPAD 8

// ---------------------------------------------------------------------------
// 1) prep: converts (vision, Wu, Wk, Wv, x) + bias fold
// ---------------------------------------------------------------------------
__device__ __forceinline__ void conv_seg(const float4* s, __nv_bfloat162* o, int n) {
    int i = blockIdx.x * 256 + threadIdx.x;
    if (i < n) {
        float4 v = s[i];
        o[2 * i]     = __floats2bfloat162_rn(v.x, v.y);
        o[2 * i + 1] = __floats2bfloat162_rn(v.z, v.w);
    }
}

__global__ void prep_kernel(const float* __restrict__ vision,
                            const float* __restrict__ Wu,
                            const float* __restrict__ bu,
                            const float* __restrict__ Wk,
                            const float* __restrict__ Wv,
                            const float* __restrict__ x) {
    switch (blockIdx.y) {
    case 0: conv_seg((const float4*)vision, (__nv_bfloat162*)g_visb, B_*V_*CV_/4); break;
    case 1: conv_seg((const float4*)Wu,     (__nv_bfloat162*)g_Wub,  CV_*DIM_/4);  break;
    case 2: conv_seg((const float4*)Wk,     (__nv_bfloat162*)g_Wkb,  DIM_*DIM_/4); break;
    case 3: conv_seg((const float4*)Wv,     (__nv_bfloat162*)g_Wvb,  DIM_*DIM_/4); break;
    case 4: conv_seg((const float4*)x,      (__nv_bfloat162*)g_xb,   B_*T_*DIM_/4); break;
    default: {   // bias fold: buk/buv = bu @ Wk/Wv; 32 blocks
        if (blockIdx.x >= 32) return;
        int kv = blockIdx.x & 1;
        const float* W = kv ? Wv : Wk;
        float* outp    = kv ? g_buv : g_buk;
        int tx = threadIdx.x & 63, ty = threadIdx.x >> 6;
        int n = (blockIdx.x >> 1) * 64 + tx;
        __shared__ float partial[4][64];
        float acc = 0.0f;
        int c0 = ty * 256;
        #pragma unroll 8
        for (int c = c0; c < c0 + 256; c++)
            acc = fmaf(bu[c], W[(size_t)c * DIM_ + n], acc);
        partial[ty][tx] = acc;
        __syncthreads();
        if (ty == 0)
            outp[n] = partial[0][tx] + partial[1][tx] + partial[2][tx] + partial[3][tx];
        break; }
    }
}

// ---------------------------------------------------------------------------
// 2a) Split-K GEMM for Wuk/Wuv (fp32 partials)
// ---------------------------------------------------------------------------
__global__ void __launch_bounds__(256)
gemm_splitk(const __nv_bfloat16* __restrict__ A,
            const __nv_bfloat16* __restrict__ B0, const __nv_bfloat16* __restrict__ B1)
{
    const int kv = blockIdx.z & 1, split = blockIdx.z >> 1;
    const __nv_bfloat16* Bm = kv ? B1 : B0;
    float* Cp = g_part[kv * SPLITS + split];
    const int N = DIM_, K = DIM_;
    const int kbase = split * SK_;

    __shared__ __align__(128) __nv_bfloat16 As[2][128][32 + APAD];
    __shared__ __align__(128) __nv_bfloat16 Bs[2][32][128 + BPAD];

    const int tid = threadIdx.x, wid = tid >> 5, lane = tid & 31;
    const int warpM = wid & 3, warpN = wid >> 2;
    const int m0 = blockIdx.y * 128, n0 = blockIdx.x * 128;
    const int NC = SK_ >> 5;

    float d[2][8][4];
    #pragma unroll
    for (int i = 0; i < 2; i++)
        #pragma unroll
        for (int j = 0; j < 8; j++)
            #pragma unroll
            for (int q = 0; q < 4; q++) d[i][j][q] = 0.0f;

    auto load_chunk = [&](int c) {
        int buf = c & 1;
        #pragma unroll
        for (int h = 0; h < 2; h++) {
            int p = h * 256 + tid;
            {
                int row = p >> 2, pc = p & 3;
                cp_async16(smem_u32(&As[buf][row][pc * 8]),
                           A + (size_t)(m0 + row) * K + kbase + c * 32 + pc * 8);
            }
            {
                int row = p >> 4, pc = p & 15;
                cp_async16(smem_u32(&Bs[buf][row][pc * 8]),
                           Bm + (size_t)(kbase + c * 32 + row) * N + n0 + pc * 8);
            }
        }
        CP_COMMIT();
    };

    load_chunk(0);

    for (int c = 0; c < NC; c++) {
        int buf = c & 1;
        if (c + 1 < NC) { load_chunk(c + 1); CP_WAIT(1); }
        else            { CP_WAIT(0); }
        __syncthreads();

        #pragma unroll
        for (int ks = 0; ks < 2; ks++) {
            uint32_t a[2][4];
            #pragma unroll
            for (int fm = 0; fm < 2; fm++) {
                int r  = warpM * 32 + fm * 16 + (lane & 7) + ((lane >> 3) & 1) * 8;
                int kk = ks * 16 + (lane >> 4) * 8;
                ldmatrix_x4(a[fm], smem_u32(&As[buf][r][kk]));
            }
            uint32_t b[8][2];
            #pragma unroll
            for (int i = 0; i < 4; i++) {
                int kk = ks * 16 + (lane & 15);
                int nn = warpN * 64 + i * 16 + (lane >> 4) * 8;
                uint32_t tmp[4];
                ldmatrix_x4_trans(tmp, smem_u32(&Bs[buf][kk][nn]));
                b[2*i][0]   = tmp[0]; b[2*i][1]   = tmp[1];
                b[2*i+1][0] = tmp[2]; b[2*i+1][1] = tmp[3];
            }
            #pragma unroll
            for (int fm = 0; fm < 2; fm++)
                #pragma unroll
                for (int fn = 0; fn < 8; fn++)
                    mma16816(d[fm][fn], a[fm], b[fn]);
        }
        __syncthreads();
    }

    const int mb = m0 + warpM * 32, nb = warpN * 64;
    #pragma unroll
    for (int fm = 0; fm < 2; fm++) {
        #pragma unroll
        for (int fn = 0; fn < 8; fn++) {
            int r0  = mb + fm * 16 + (lane >> 2);
            int col = n0 + nb + fn * 8 + 2 * (lane & 3);
            *(float2*)(Cp + (size_t)r0 * N + col)       = make_float2(d[fm][fn][0], d[fm][fn][1]);
            *(float2*)(Cp + (size_t)(r0 + 8) * N + col) = make_float2(d[fm][fn][2], d[fm][fn][3]);
        }
    }
}

// 2b) Reduce split-K partials -> bf16 Wuk/Wuv; y==2: bdot[t] = buk . x[t]
__global__ void reduce_bdot_kernel(const float* __restrict__ x) {
    if (blockIdx.y < 2) {
        if (blockIdx.x >= 256) return;
        int i  = blockIdx.x * 256 + threadIdx.x;
        int kv = blockIdx.y;
        float4 acc = make_float4(0.f, 0.f, 0.f, 0.f);
        #pragma unroll
        for (int s = 0; s < SPLITS; s++) {
            float4 p = ((const float4*)g_part[kv * SPLITS + s])[i];
            acc.x += p.x; acc.y += p.y; acc.z += p.z; acc.w += p.w;
        }
        __nv_bfloat162* o = (__nv_bfloat162*)(kv ? g_Wuv : g_Wuk);
        o[2 * i]     = __floats2bfloat162_rn(acc.x, acc.y);
        o[2 * i + 1] = __floats2bfloat162_rn(acc.z, acc.w);
    } else {
        int t = blockIdx.x;                       // 0..1023 (b*T+t)
        int tid = threadIdx.x;
        __shared__ float sh[256];
        float acc = 0.0f;
        const float* xr = x + (size_t)t * DIM_;
        #pragma unroll
        for (int i = tid; i < DIM_; i += 256)
            acc = fmaf(g_buk[i], xr[i], acc);
        sh[tid] = acc; __syncthreads();
        for (int s = 128; s > 0; s >>= 1) {
            if (tid < s) sh[tid] += sh[tid + s];
            __syncthreads();
        }
        if (tid == 0) g_bdot[t] = sh[0];
    }
}

// ---------------------------------------------------------------------------
// 3) gemm_nt: C = A[M,K] @ B[N,K]^T ; B row-major [N,K] (non-trans ldmatrix)
//    mode 0: write bf16.  mode 1: write fp32 (acc+bdot[z*M+r])/32 - 100.
// ---------------------------------------------------------------------------
#define NT_A_ELEMS (128 * 72)
#define NT_STAGE   (2 * NT_A_ELEMS * 2)          // A + B, bytes
#define NT_SMEM    (2 * NT_STAGE)                // 73728

__global__ void __launch_bounds__(256)
gemm_nt(const __nv_bfloat16* __restrict__ Ag, const __nv_bfloat16* __restrict__ Bg,
        void* Cv, int M, int N, int K,
        long zsA, long zsB, long zsC, int mode, const float* __restrict__ bdot)
{
    const __nv_bfloat16* A = Ag + (size_t)blockIdx.z * zsA;
    const __nv_bfloat16* Bm = Bg + (size_t)blockIdx.z * zsB;

    extern __shared__ char dsm[];
    auto Aadr = [&](int s, int r, int c) {
        return (__nv_bfloat16*)(dsm + s * NT_STAGE) + r * 72 + c;
    };
    auto Badr = [&](int s, int r, int c) {
        return (__nv_bfloat16*)(dsm + s * NT_STAGE + NT_A_ELEMS * 2) + r * 72 + c;
    };

    const int tid = threadIdx.x, wid = tid >> 5, lane = tid & 31;
    const int warpM = wid & 3, warpN = wid >> 2;
    const int m0 = blockIdx.y * 128, n0 = blockIdx.x * 128;
    const int NC = K >> 6;

    float d[2][8][4];
    #pragma unroll
    for (int i = 0; i < 2; i++)
        #pragma unroll
        for (int j = 0; j < 8; j++)
            #pragma unroll
            for (int q = 0; q < 4; q++) d[i][j][q] = 0.0f;

    auto load_chunk = [&](int c) {
        int buf = c & 1;
        #pragma unroll
        for (int h = 0; h < 4; h++) {
            int p = h * 256 + tid;
            int row = p >> 3, pc = p & 7;
            cp_async16(smem_u32(Aadr(buf, row, pc * 8)),
                       A + (size_t)(m0 + row) * K + c * 64 + pc * 8);
            cp_async16(smem_u32(Badr(buf, row, pc * 8)),
                       Bm + (size_t)(n0 + row) * K + c * 64 + pc * 8);
        }
        CP_COMMIT();
    };

    load_chunk(0);

    for (int c = 0; c < NC; c++) {
        int buf = c & 1;
        if (c + 1 < NC) { load_chunk(c + 1); CP_WAIT(1); }
        else            { CP_WAIT(0); }
        __syncthreads();

        #pragma unroll
        for (int ks = 0; ks < 4; ks++) {
            uint32_t a[2][4];
            #pragma unroll
            for (int fm = 0; fm < 2; fm++) {
                int r  = warpM * 32 + fm * 16 + (lane & 7) + ((lane >> 3) & 1) * 8;
                int kk = ks * 16 + (lane >> 4) * 8;
                ldmatrix_x4(a[fm], smem_u32(Aadr(buf, r, kk)));
            }
            uint32_t b[8][2];
            #pragma unroll
            for (int i = 0; i < 4; i++) {
                int r  = warpN * 64 + i * 16 + (lane & 7) + (lane >> 4) * 8;
                int kk = ks * 16 + ((lane >> 3) & 1) * 8;
                uint32_t tmp[4];
                ldmatrix_x4(tmp, smem_u32(Badr(buf, r, kk)));
                b[2*i][0]   = tmp[0]; b[2*i][1]   = tmp[1];
                b[2*i+1][0] = tmp[2]; b[2*i+1][1] = tmp[3];
            }
            #pragma unroll
            for (int fm = 0; fm < 2; fm++)
                #pragma unroll
                for (int fn = 0; fn < 8; fn++)
                    mma16816(d[fm][fn], a[fm], b[fn]);
        }
        __syncthreads();
    }

    const int mb = m0 + warpM * 32, nb = warpN * 64;
    #pragma unroll
    for (int fm = 0; fm < 2; fm++) {
        #pragma unroll
        for (int fn = 0; fn < 8; fn++) {
            int r0  = mb + fm * 16 + (lane >> 2);
            int col = nb + fn * 8 + 2 * (lane & 3);
            if (mode == 0) {
                __nv_bfloat16* C = (__nv_bfloat16*)Cv + (size_t)blockIdx.z * zsC;
                *(__nv_bfloat162*)(C + (size_t)r0 * N + n0 + col) =
                    __floats2bfloat162_rn(d[fm][fn][0], d[fm][fn][1]);
                *(__nv_bfloat162*)(C + (size_t)(r0 + 8) * N + n0 + col) =
                    __floats2bfloat162_rn(d[fm][fn][2], d[fm][fn][3]);
            } else {
                float* C = (float*)Cv + (size_t)blockIdx.z * zsC;
                float bd0 = bdot[blockIdx.z * M + r0];
                float bd1 = bdot[blockIdx.z * M + r0 + 8];
                *(float2*)(C + (size_t)r0 * N + n0 + col) =
                    make_float2((d[fm][fn][0] + bd0) * 0.03125f - 100.0f,
                                (d[fm][fn][1] + bd0) * 0.03125f - 100.0f);
                *(float2*)(C + (size_t)(r0 + 8) * N + n0 + col) =
                    make_float2((d[fm][fn][2] + bd1) * 0.03125f - 100.0f,
                                (d[fm][fn][3] + bd1) * 0.03125f - 100.0f);
            }
        }
    }
}

// ---------------------------------------------------------------------------
// 4) gemm_tn2: C = A[M,K] @ B[K,N] ; B row-major [K,N] (trans ldmatrix)
//    mode 0: bf16 out. mode 2: fp32 out = acc + xres + wsum[r]*buv[col].
// ---------------------------------------------------------------------------
#define TN_A_ELEMS (128 * 72)
#define TN_B_ELEMS (64 * 136)
#define TN_STAGE   ((TN_A_ELEMS + TN_B_ELEMS) * 2)
#define TN_SMEM    (2 * TN_STAGE)                // 71680

__global__ void __launch_bounds__(256)
gemm_tn2(const __nv_bfloat16* __restrict__ Ag, const __nv_bfloat16* __restrict__ Bg,
         void* Cv, int M, int N, int K,
         long zsA, long zsB, long zsC, int mode,
         const float* __restrict__ xres, const float* __restrict__ wsum,
         const float* __restrict__ buv)
{
    const __nv_bfloat16* A = Ag + (size_t)blockIdx.z * zsA;
    const __nv_bfloat16* Bm = Bg + (size_t)blockIdx.z * zsB;

    extern __shared__ char dsm[];
    __shared__ float bsm[128];
    auto Aadr = [&](int s, int r, int c) {
        return (__nv_bfloat16*)(dsm + s * TN_STAGE) + r * 72 + c;
    };
    auto Badr = [&](int s, int r, int c) {
        return (__nv_bfloat16*)(dsm + s * TN_STAGE + TN_A_ELEMS * 2) + r * 136 + c;
    };

    const int tid = threadIdx.x, wid = tid >> 5, lane = tid & 31;
    const int warpM = wid & 3, warpN = wid >> 2;
    const int m0 = blockIdx.y * 128, n0 = blockIdx.x * 128;
    const int NC = K >> 6;

    if (mode == 2 && tid < 128) bsm[tid] = buv[n0 + tid];

    float d[2][8][4];
    #pragma unroll
    for (int i = 0; i < 2; i++)
        #pragma unroll
        for (int j = 0; j < 8; j++)
            #pragma unroll
            for (int q = 0; q < 4; q++) d[i][j][q] = 0.0f;

    auto load_chunk = [&](int c) {
        int buf = c & 1;
        #pragma unroll
        for (int h = 0; h < 4; h++) {
            int p = h * 256 + tid;
            {
                int row = p >> 3, pc = p & 7;
                cp_async16(smem_u32(Aadr(buf, row, pc * 8)),
                           A + (size_t)(m0 + row) * K + c * 64 + pc * 8);
            }
            {
                int row = p >> 4, pc = p & 15;
                cp_async16(smem_u32(Badr(buf, row, pc * 8)),
                           Bm + (size_t)(c * 64 + row) * N + n0 + pc * 8);
            }
        }
        CP_COMMIT();
    };

    load_chunk(0);

    for (int c = 0; c < NC; c++) {
        int buf = c & 1;
        if (c + 1 < NC) { load_chunk(c + 1); CP_WAIT(1); }
        else            { CP_WAIT(0); }
        __syncthreads();

        #pragma unroll
        for (int ks = 0; ks < 4; ks++) {
            uint32_t a[2][4];
            #pragma unroll
            for (int fm = 0; fm < 2; fm++) {
                int r  = warpM * 32 + fm * 16 + (lane & 7) + ((lane >> 3) & 1) * 8;
                int kk = ks * 16 + (lane >> 4) * 8;
                ldmatrix_x4(a[fm], smem_u32(Aadr(buf, r, kk)));
            }
            uint32_t b[8][2];
            #pragma unroll
            for (int i = 0; i < 4; i++) {
                int kk = ks * 16 + (lane & 15);
                int nn = warpN * 64 + i * 16 + (lane >> 4) * 8;
                uint32_t tmp[4];
                ldmatrix_x4_trans(tmp, smem_u32(Badr(buf, kk, nn)));
                b[2*i][0]   = tmp[0]; b[2*i][1]   = tmp[1];
                b[2*i+1][0] = tmp[2]; b[2*i+1][1] = tmp[3];
            }
            #pragma unroll
            for (int fm = 0; fm < 2; fm++)
                #pragma unroll
                for (int fn = 0; fn < 8; fn++)
                    mma16816(d[fm][fn], a[fm], b[fn]);
        }
        __syncthreads();
    }

    const int mb = m0 + warpM * 32, nb = warpN * 64;
    #pragma unroll
    for (int fm = 0; fm < 2; fm++) {
        #pragma unroll
        for (int fn = 0; fn < 8; fn++) {
            int r0  = mb + fm * 16 + (lane >> 2);
            int col = nb + fn * 8 + 2 * (lane & 3);
            if (mode == 0) {
                __nv_bfloat16* C = (__nv_bfloat16*)Cv + (size_t)blockIdx.z * zsC;
                *(__nv_bfloat162*)(C + (size_t)r0 * N + n0 + col) =
                    __floats2bfloat162_rn(d[fm][fn][0], d[fm][fn][1]);
                *(__nv_bfloat162*)(C + (size_t)(r0 + 8) * N + n0 + col) =
                    __floats2bfloat162_rn(d[fm][fn][2], d[fm][fn][3]);
            } else {
                float* C = (float*)Cv + (size_t)blockIdx.z * zsC;
                float ws0 = wsum[r0], ws1 = wsum[r0 + 8];
                float b0 = bsm[col], b1 = bsm[col + 1];
                float2 x0 = *(const float2*)(xres + (size_t)r0 * N + n0 + col);
                float2 x1 = *(const float2*)(xres + (size_t)(r0 + 8) * N + n0 + col);
                *(float2*)(C + (size_t)r0 * N + n0 + col) =
                    make_float2(d[fm][fn][0] + x0.x + ws0 * b0,
                                d[fm][fn][1] + x0.y + ws0 * b1);
                *(float2*)(C + (size_t)(r0 + 8) * N + n0 + col) =
                    make_float2(d[fm][fn][2] + x1.x + ws1 * b0,
                                d[fm][fn][3] + x1.y + ws1 * b1);
            }
        }
    }
}

// ---------------------------------------------------------------------------
// 5) stats: per-(b,t) masked (max, sumexp) over dense logits
// ---------------------------------------------------------------------------
__global__ void stats_kernel(const int* __restrict__ mask) {
    int bt = blockIdx.x, b = bt >> 8, t = bt & 255;
    int tid = threadIdx.x;
    __shared__ float sm[256], ss[256];

    float m = -1e30f, s = 0.0f;
    const float* L = g_logitD + (size_t)bt * V_;
    const int* mc = mask + (size_t)b * V_ * T_ + t;
    #pragma unroll
    for (int i = tid; i < V_; i += 256) {
        if (mc[(size_t)i * T_] != 0) {
            float lg = L[i];
            float nm = fmaxf(m, lg);
            s = s * __expf(m - nm) + __expf(lg - nm);
            m = nm;
        }
    }
    sm[tid] = m; ss[tid] = s;
    __syncthreads();
    for (int st = 128; st > 0; st >>= 1) {
        if (tid < st) {
            float m2 = sm[tid + st], s2 = ss[tid + st];
            float nm = fmaxf(sm[tid], m2);
            ss[tid] = ss[tid] * __expf(sm[tid] - nm) + s2 * __expf(m2 - nm);
            sm[tid] = nm;
        }
        __syncthreads();
    }
    if (tid == 0) g_ms[bt] = make_float2(sm[0], ss[0]);
}

// ---------------------------------------------------------------------------
// 6) wgen: batch-combine stats; w = mask ? exp(lg - M)/S : 0; wsum row total
// ---------------------------------------------------------------------------
__global__ void wgen_kernel(const int* __restrict__ mask) {
    int bt = blockIdx.x, b = bt >> 8, t = bt & 255;
    int tid = threadIdx.x;
    __shared__ float shm[256], shs[256];

    float2 v = g_ms[b * T_ + tid];
    shm[tid] = v.x;
    __syncthreads();
    for (int st = 128; st > 0; st >>= 1) {
        if (tid < st) shm[tid] = fmaxf(shm[tid], shm[tid + st]);
        __syncthreads();
    }
    float M = shm[0];
    shs[tid] = v.y * __expf(v.x - M);
    __syncthreads();
    for (int st = 128; st > 0; st >>= 1) {
        if (tid < st) shs[tid] += shs[tid + st];
        __syncthreads();
    }
    float inv = 1.0f / shs[0];
    __syncthreads();

    const float* L = g_logitD + (size_t)bt * V_;
    const int* mc = mask + (size_t)b * V_ * T_ + t;
    __nv_bfloat16* W = g_w + (size_t)bt * V_;
    float wsum = 0.0f;
    #pragma unroll
    for (int i = tid; i < V_; i += 256) {
        float w = 0.0f;
        if (mc[(size_t)i * T_] != 0) w = __expf(L[i] - M) * inv;
        W[i] = __float2bfloat16(w);
        wsum += w;
    }
    shs[tid] = wsum;
    __syncthreads();
    for (int st = 128; st > 0; st >>= 1) {
        if (tid < st) shs[tid] += shs[tid + st];
        __syncthreads();
    }
    if (tid == 0) g_wsum[bt] = shs[0];
}

// ---------------------------------------------------------------------------
// Launch
// ---------------------------------------------------------------------------
extern "C" void kernel_launch(void* const* d_in, const int* in_sizes, int n_in,
                              void* d_out, int out_size)
{
    const float* x      = (const float*)d_in[0];
    const float* vision = (const float*)d_in[1];
    const int*   mask   = (const int*)  d_in[2];
    const float* Wu     = (const float*)d_in[3];
    const float* bu     = (const float*)d_in[4];
    const float* Wk     = (const float*)d_in[5];
    const float* Wv     = (const float*)d_in[6];
    float* out = (float*)d_out;

    void *pvb, *pxb, *pwu, *pwk, *pwv, *puk, *puv, *pbv, *pbd, *pxq, *plg, *pw, *pws, *pag;
    cudaGetSymbolAddress(&pvb, g_visb);
    cudaGetSymbolAddress(&pxb, g_xb);
    cudaGetSymbolAddress(&pwu, g_Wub);
    cudaGetSymbolAddress(&pwk, g_Wkb);
    cudaGetSymbolAddress(&pwv, g_Wvb);
    cudaGetSymbolAddress(&puk, g_Wuk);
    cudaGetSymbolAddress(&puv, g_Wuv);
    cudaGetSymbolAddress(&pbv, g_buv);
    cudaGetSymbolAddress(&pbd, g_bdot);
    cudaGetSymbolAddress(&pxq, g_xq);
    cudaGetSymbolAddress(&plg, g_logitD);
    cudaGetSymbolAddress(&pw,  g_w);
    cudaGetSymbolAddress(&pws, g_wsum);
    cudaGetSymbolAddress(&pag, g_agg);

    static int smem_set = 0;
    if (!smem_set) {
        cudaFuncSetAttribute(gemm_nt,  cudaFuncAttributeMaxDynamicSharedMemorySize, NT_SMEM);
        cudaFuncSetAttribute(gemm_tn2, cudaFuncAttributeMaxDynamicSharedMemorySize, TN_SMEM);
        smem_set = 1;
    }

    // 1) converts + bias fold
    prep_kernel<<<dim3(1024, 6), 256>>>(vision, Wu, bu, Wk, Wv, x);

    // 2) Wuk/Wuv = Wu@Wk/Wv (split-K) ; reduce + bdot
    gemm_splitk<<<dim3(DIM_/128, CV_/128, 2*SPLITS), 256>>>(
        (const __nv_bfloat16*)pwu,
        (const __nv_bfloat16*)pwk, (const __nv_bfloat16*)pwv);
    reduce_bdot_kernel<<<dim3(1024, 3), 256>>>(x);

    // 3) xq = x @ Wuk^T  (M=1024, N=256, K=1024; B=[N,K] row-major)
    gemm_nt<<<dim3(CV_/128, (B_*T_)/128, 1), 256, NT_SMEM>>>(
        (const __nv_bfloat16*)pxb, (const __nv_bfloat16*)puk, pxq,
        B_*T_, CV_, DIM_, 0, 0, 0, 0, nullptr);

    // 4) dense logits: QK[b][t,v] = (xq . vision)/32 + bdot/32 - 100
    gemm_nt<<<dim3(V_/128, T_/128, B_), 256, NT_SMEM>>>(
        (const __nv_bfloat16*)pxq, (const __nv_bfloat16*)pvb, plg,
        T_, V_, CV_, (long)T_*CV_, (long)V_*CV_, (long)T_*V_, 1, (const float*)pbd);

    // 5) masked batch softmax: stats, then weights
    stats_kernel<<<B_*T_, 256>>>(mask);
    wgen_kernel<<<B_*T_, 256>>>(mask);

    // 6) agg[b][t,c] = w @ vision  (M=256, N=256, K=1024; B=[K,N] row-major)
    gemm_tn2<<<dim3(CV_/128, T_/128, B_), 256, TN_SMEM>>>(
        (const __nv_bfloat16*)pw, (const __nv_bfloat16*)pvb, pag,
        T_, CV_, V_, (long)T_*V_, (long)V_*CV_, (long)T_*CV_, 0,
        nullptr, nullptr, nullptr);

    // 7) out = x + agg @ Wuv + wsum*buv  (M=1024, N=1024, K=256)
    gemm_tn2<<<dim3(DIM_/128, (B_*T_)/128, 1), 256, TN_SMEM>>>(
        (const __nv_bfloat16*)pag, (const __nv_bfloat16*)puv, out,
        B_*T_, DIM_, CV_, 0, 0, 0, 2,
        x, (const float*)pws, (const float*)pbv);
}

// round 10
// speedup vs baseline: 1.1623x; 1.1623x over previous
#include <cuda_runtime.h>
#include <cuda_bf16.h>
#include <cstdint>
#include <math.h>

#define B_   4
#define T_   256
#define V_   1024
#define DIM_ 1024
#define CV_  256
#define NCTA 148

// ---------------------------------------------------------------------------
// Scratch (static device globals)
// ---------------------------------------------------------------------------
__device__ __nv_bfloat16 g_visb[B_ * V_ * CV_];   // vision bf16
__device__ __nv_bfloat16 g_xb  [B_ * T_ * DIM_]; // x bf16
__device__ __nv_bfloat16 g_Wub [CV_ * DIM_];
__device__ __nv_bfloat16 g_Wkb [DIM_ * DIM_];
__device__ __nv_bfloat16 g_Wvb [DIM_ * DIM_];
__device__ __nv_bfloat16 g_Wuk [CV_ * DIM_];      // Wu@Wk
__device__ __nv_bfloat16 g_Wuv [CV_ * DIM_];      // Wu@Wv
__device__ float         g_part[8][CV_ * DIM_];   // split-K partials (8MB, reused 3x)
__device__ float         g_buk [DIM_];
__device__ float         g_buv [DIM_];
__device__ float         g_bdot[B_ * T_];
__device__ __nv_bfloat16 g_xq  [B_ * T_ * CV_];
__device__ float         g_logitD[B_ * T_ * V_];
__device__ unsigned      g_maskT [B_ * T_ * (V_ / 32)]; // bit-packed (b,t,v)
__device__ __nv_bfloat16 g_w   [B_ * T_ * V_];
__device__ float         g_wsum[B_ * T_];
__device__ __nv_bfloat16 g_agg [B_ * T_ * CV_];
__device__ float2        g_ms  [B_ * T_];
__device__ unsigned      g_bar_cnt;
__device__ unsigned      g_bar_gen;

// ---------------------------------------------------------------------------
// helpers
// ---------------------------------------------------------------------------
__device__ __forceinline__ uint32_t smem_u32(const void* p) {
    uint32_t a;
    asm("{ .reg .u64 t; cvta.to.shared.u64 t, %1; cvt.u32.u64 %0, t; }"
        : "=r"(a) : "l"(p));
    return a;
}
__device__ __forceinline__ void cp_async16(uint32_t dst, const void* src) {
    asm volatile("cp.async.cg.shared.global [%0], [%1], 16;" :: "r"(dst), "l"(src));
}
#define CP_COMMIT() asm volatile("cp.async.commit_group;" ::: "memory")
#define CP_WAIT(n)  asm volatile("cp.async.wait_group %0;" :: "n"(n) : "memory")

__device__ __forceinline__ void ldmatrix_x4(uint32_t* r, uint32_t addr) {
    asm volatile("ldmatrix.sync.aligned.m8n8.x4.shared.b16 {%0,%1,%2,%3}, [%4];"
                 : "=r"(r[0]), "=r"(r[1]), "=r"(r[2]), "=r"(r[3]) : "r"(addr));
}
__device__ __forceinline__ void ldmatrix_x4_trans(uint32_t* r, uint32_t addr) {
    asm volatile("ldmatrix.sync.aligned.m8n8.x4.trans.shared.b16 {%0,%1,%2,%3}, [%4];"
                 : "=r"(r[0]), "=r"(r[1]), "=r"(r[2]), "=r"(r[3]) : "r"(addr));
}
__device__ __forceinline__ void mma16816(float* d, const uint32_t* a, const uint32_t* b) {
    asm volatile(
        "mma.sync.aligned.m16n8k16.row.col.f32.bf16.bf16.f32 "
        "{%0,%1,%2,%3},{%4,%5,%6,%7},{%8,%9},{%0,%1,%2,%3};"
        : "+f"(d[0]), "+f"(d[1]), "+f"(d[2]), "+f"(d[3])
        : "r"(a[0]), "r"(a[1]), "r"(a[2]), "r"(a[3]), "r"(b[0]), "r"(b[1]));
}

// grid-wide barrier (all NCTA CTAs co-resident: 1 CTA/SM)
__device__ __forceinline__ void grid_sync() {
    __syncthreads();
    if (threadIdx.x == 0) {
        volatile unsigned* vgen = &g_bar_gen;
        unsigned gen = *vgen;
        __threadfence();
        if (atomicAdd(&g_bar_cnt, 1u) == NCTA - 1) {
            g_bar_cnt = 0u;
            __threadfence();
            *(volatile unsigned*)&g_bar_gen = gen + 1u;
        } else {
            while (*vgen == gen) { }
        }
        __threadfence();
    }
    __syncthreads();
}

__device__ __forceinline__ void ms_comb(float& m, float& s, float m2, float s2) {
    float nm = fmaxf(m, m2);
    s = s * __expf(m - nm) + s2 * __expf(m2 - nm);
    m = nm;
}
__device__ __forceinline__ void st_bf16x4(__nv_bfloat162* o, int i, float4 a) {
    o[2 * i]     = __floats2bfloat162_rn(a.x, a.y);
    o[2 * i + 1] = __floats2bfloat162_rn(a.z, a.w);
}

// ---------------------------------------------------------------------------
// GEMM tile cores (128x128 tile, 256 threads). Caller pre-offsets A,B to tile.
// ---------------------------------------------------------------------------
#define TN_AE 9216                    // A elems per stage (128*72)
#define TN_ST 35840                   // TN stage bytes (A 18432 + B 64*136*2)
#define NT_ST 36864                   // NT stage bytes (A 18432 + B 18432)
#define DSM_BYTES 73728

// TN: C += A[128,K] @ B[K,128];  A row-major lda, B row-major ldb
__device__ __forceinline__ void tile_tn(const __nv_bfloat16* __restrict__ A, int lda,
                                        const __nv_bfloat16* __restrict__ Bm, int ldb,
                                        int nchunks, char* dsm, float d[2][8][4]) {
    const int tid = threadIdx.x, lane = tid & 31, wid = tid >> 5;
    const int warpM = wid & 3, warpN = wid >> 2;
    auto Aadr = [&](int s, int r, int c) { return (__nv_bfloat16*)(dsm + s * TN_ST) + r * 72 + c; };
    auto Badr = [&](int s, int r, int c) { return (__nv_bfloat16*)(dsm + s * TN_ST + TN_AE * 2) + r * 136 + c; };
    #pragma unroll
    for (int i = 0; i < 2; i++)
        #pragma unroll
        for (int j = 0; j < 8; j++)
            #pragma unroll
            for (int q = 0; q < 4; q++) d[i][j][q] = 0.0f;

    auto load_chunk = [&](int c) {
        int buf = c & 1;
        #pragma unroll
        for (int h = 0; h < 4; h++) {
            int p = h * 256 + tid;
            { int row = p >> 3, pc = p & 7;
              cp_async16(smem_u32(Aadr(buf, row, pc * 8)), A + (size_t)row * lda + c * 64 + pc * 8); }
            { int row = p >> 4, pc = p & 15;
              cp_async16(smem_u32(Badr(buf, row, pc * 8)), Bm + (size_t)(c * 64 + row) * ldb + pc * 8); }
        }
        CP_COMMIT();
    };
    load_chunk(0);
    for (int c = 0; c < nchunks; c++) {
        int buf = c & 1;
        if (c + 1 < nchunks) { load_chunk(c + 1); CP_WAIT(1); }
        else                 { CP_WAIT(0); }
        __syncthreads();
        #pragma unroll
        for (int ks = 0; ks < 4; ks++) {
            uint32_t a[2][4];
            #pragma unroll
            for (int fm = 0; fm < 2; fm++) {
                int r  = warpM * 32 + fm * 16 + (lane & 7) + ((lane >> 3) & 1) * 8;
                int kk = ks * 16 + (lane >> 4) * 8;
                ldmatrix_x4(a[fm], smem_u32(Aadr(buf, r, kk)));
            }
            uint32_t b[8][2];
            #pragma unroll
            for (int i = 0; i < 4; i++) {
                int kk = ks * 16 + (lane & 15);
                int nn = warpN * 64 + i * 16 + (lane >> 4) * 8;
                uint32_t tmp[4];
                ldmatrix_x4_trans(tmp, smem_u32(Badr(buf, kk, nn)));
                b[2*i][0]   = tmp[0]; b[2*i][1]   = tmp[1];
                b[2*i+1][0] = tmp[2]; b[2*i+1][1] = tmp[3];
            }
            #pragma unroll
            for (int fm = 0; fm < 2; fm++)
                #pragma unroll
                for (int fn = 0; fn < 8; fn++)
                    mma16816(d[fm][fn], a[fm], b[fn]);
        }
        __syncthreads();
    }
}

// NT: C += A[128,K] @ B[128,K]^T;  both row-major
__device__ __forceinline__ void tile_nt(const __nv_bfloat16* __restrict__ A, int lda,
                                        const __nv_bfloat16* __restrict__ Bm, int ldb,
                                        int nchunks, char* dsm, float d[2][8][4]) {
    const int tid = threadIdx.x, lane = tid & 31, wid = tid >> 5;
    const int warpM = wid & 3, warpN = wid >> 2;
    auto Aadr = [&](int s, int r, int c) { return (__nv_bfloat16*)(dsm + s * NT_ST) + r * 72 + c; };
    auto Badr = [&](int s, int r, int c) { return (__nv_bfloat16*)(dsm + s * NT_ST + TN_AE * 2) + r * 72 + c; };
    #pragma unroll
    for (int i = 0; i < 2; i++)
        #pragma unroll
        for (int j = 0; j < 8; j++)
            #pragma unroll
            for (int q = 0; q < 4; q++) d[i][j][q] = 0.0f;

    auto load_chunk = [&](int c) {
        int buf = c & 1;
        #pragma unroll
        for (int h = 0; h < 4; h++) {
            int p = h * 256 + tid;
            int row = p >> 3, pc = p & 7;
            cp_async16(smem_u32(Aadr(buf, row, pc * 8)), A + (size_t)row * lda + c * 64 + pc * 8);
            cp_async16(smem_u32(Badr(buf, row, pc * 8)), Bm + (size_t)row * ldb + c * 64 + pc * 8);
        }
        CP_COMMIT();
    };
    load_chunk(0);
    for (int c = 0; c < nchunks; c++) {
        int buf = c & 1;
        if (c + 1 < nchunks) { load_chunk(c + 1); CP_WAIT(1); }
        else                 { CP_WAIT(0); }
        __syncthreads();
        #pragma unroll
        for (int ks = 0; ks < 4; ks++) {
            uint32_t a[2][4];
            #pragma unroll
            for (int fm = 0; fm < 2; fm++) {
                int r  = warpM * 32 + fm * 16 + (lane & 7) + ((lane >> 3) & 1) * 8;
                int kk = ks * 16 + (lane >> 4) * 8;
                ldmatrix_x4(a[fm], smem_u32(Aadr(buf, r, kk)));
            }
            uint32_t b[8][2];
            #pragma unroll
            for (int i = 0; i < 4; i++) {
                int r  = warpN * 64 + i * 16 + (lane & 7) + (lane >> 4) * 8;
                int kk = ks * 16 + ((lane >> 3) & 1) * 8;
                uint32_t tmp[4];
                ldmatrix_x4(tmp, smem_u32(Badr(buf, r, kk)));
                b[2*i][0]   = tmp[0]; b[2*i][1]   = tmp[1];
                b[2*i+1][0] = tmp[2]; b[2*i+1][1] = tmp[3];
            }
            #pragma unroll
            for (int fm = 0; fm < 2; fm++)
                #pragma unroll
                for (int fn = 0; fn < 8; fn++)
                    mma16816(d[fm][fn], a[fm], b[fn]);
        }
        __syncthreads();
    }
}

// variadic: bodies contain commas
#define FRAG_LOOP(...) \
    { const int lane_ = threadIdx.x & 31, wid_ = threadIdx.x >> 5; \
      const int warpM_ = wid_ & 3, warpN_ = wid_ >> 2; \
      _Pragma("unroll") for (int fm = 0; fm < 2; fm++) \
      _Pragma("unroll") for (int fn = 0; fn < 8; fn++) { \
          int r0  = warpM_ * 32 + fm * 16 + (lane_ >> 2); \
          int col = warpN_ * 64 + fn * 8 + 2 * (lane_ & 3); \
          __VA_ARGS__ } }

// ---------------------------------------------------------------------------
// The persistent mega-kernel
// ---------------------------------------------------------------------------
extern "C" __global__ void __launch_bounds__(256)
mega_kernel(const float* __restrict__ x, const float* __restrict__ vision,
            const int* __restrict__ mask, const float* __restrict__ Wu,
            const float* __restrict__ bu, const float* __restrict__ Wk,
            const float* __restrict__ Wv, float* __restrict__ out)
{
    extern __shared__ char dsm[];
    const int cta = blockIdx.x, tid = threadIdx.x;
    const int lane = tid & 31, wid = tid >> 5;

    // ============ P0: converts + maskT bitpack + bias fold ============
    if (cta < 116) {
        const int stride = 116 * 256;
        int base = cta * 256 + tid;
        for (int i = base; i < B_*V_*CV_/4; i += stride) {
            float4 v = ((const float4*)vision)[i];
            st_bf16x4((__nv_bfloat162*)g_visb, i, v);
        }
        for (int i = base; i < CV_*DIM_/4; i += stride) {
            float4 v = ((const float4*)Wu)[i];
            st_bf16x4((__nv_bfloat162*)g_Wub, i, v);
        }
        for (int i = base; i < DIM_*DIM_/4; i += stride) {
            float4 v = ((const float4*)Wk)[i];
            st_bf16x4((__nv_bfloat162*)g_Wkb, i, v);
        }
        for (int i = base; i < DIM_*DIM_/4; i += stride) {
            float4 v = ((const float4*)Wv)[i];
            st_bf16x4((__nv_bfloat162*)g_Wvb, i, v);
        }
        for (int i = base; i < B_*T_*DIM_/4; i += stride) {
            float4 v = ((const float4*)x)[i];
            st_bf16x4((__nv_bfloat162*)g_xb, i, v);
        }
        // maskT: bit v of word = mask[b, v, t]; tiles of 32 v x 256 t
        int* tile = (int*)dsm;   // [32][257]
        for (int job = cta; job < 128; job += 116) {
            int b = job >> 5, v0 = (job & 31) * 32;
            const int* mp = mask + (size_t)b * V_ * T_;
            __syncthreads();
            #pragma unroll
            for (int vr = 0; vr < 32; vr++)
                tile[vr * 257 + tid] = mp[(size_t)(v0 + vr) * T_ + tid];
            __syncthreads();
            unsigned word = 0;
            #pragma unroll
            for (int vr = 0; vr < 32; vr++)
                word |= (tile[vr * 257 + tid] != 0 ? 1u : 0u) << vr;
            g_maskT[((size_t)b * T_ + tid) * 32 + (job & 31)] = word;
        }
    } else {
        // bias fold: buk/buv = bu @ Wk/Wv; 32 CTAs, each 64 outputs, 4-way K split
        int idx = cta - 116;                   // 0..31
        int kv = idx & 1, n0b = (idx >> 1) * 64;
        const float* W = kv ? Wv : Wk;
        int tx = tid & 63, ty = tid >> 6;
        float acc = 0.0f;
        int c0 = ty * 256;
        #pragma unroll 8
        for (int c = c0; c < c0 + 256; c++)
            acc = fmaf(bu[c], W[(size_t)c * DIM_ + n0b + tx], acc);
        float* sp = (float*)dsm;
        sp[ty * 64 + tx] = acc;
        __syncthreads();
        if (ty == 0)
            (kv ? g_buv : g_buk)[n0b + tx] = sp[tx] + sp[64+tx] + sp[128+tx] + sp[192+tx];
    }
    grid_sync();

    // ============ P1: Wuk/Wuv = Wu @ Wk/Wv, split-K=4 (128 jobs) ============
    if (cta < 128) {
        int kv = cta & 1, split = (cta >> 1) & 3, mt = (cta >> 3) & 1, nt = cta >> 4;
        int kbase = split * 256, m0 = mt * 128, n0 = nt * 128;
        const __nv_bfloat16* A = g_Wub + (size_t)m0 * DIM_ + kbase;
        const __nv_bfloat16* Bm = (kv ? g_Wvb : g_Wkb) + (size_t)kbase * DIM_ + n0;
        float d[2][8][4];
        tile_tn(A, DIM_, Bm, DIM_, 4, dsm, d);
        float* Cp = g_part[kv * 4 + split];
        FRAG_LOOP(
            *(float2*)(Cp + (size_t)(m0 + r0) * DIM_ + n0 + col)     = make_float2(d[fm][fn][0], d[fm][fn][1]);
            *(float2*)(Cp + (size_t)(m0 + r0 + 8) * DIM_ + n0 + col) = make_float2(d[fm][fn][2], d[fm][fn][3]); )
    }
    grid_sync();

    // ============ P2: reduce Wuk/Wuv -> bf16 ; bdot = buk . x[t] ============
    for (int i = cta * 256 + tid; i < 131072; i += NCTA * 256) {
        int kv = i >> 16, j = i & 65535;
        float4 a = make_float4(0.f, 0.f, 0.f, 0.f);
        #pragma unroll
        for (int s = 0; s < 4; s++) {
            float4 p = ((const float4*)g_part[kv * 4 + s])[j];
            a.x += p.x; a.y += p.y; a.z += p.z; a.w += p.w;
        }
        st_bf16x4((__nv_bfloat162*)(kv ? g_Wuv : g_Wuk), j, a);
    }
    {
        int bt = cta * 8 + wid;
        if (bt < B_ * T_) {
            const float* xr = x + (size_t)bt * DIM_;
            float acc = 0.0f;
            #pragma unroll
            for (int k = 0; k < 32; k++)
                acc = fmaf(xr[k * 32 + lane], g_buk[k * 32 + lane], acc);
            #pragma unroll
            for (int off = 16; off > 0; off >>= 1)
                acc += __shfl_down_sync(0xffffffffu, acc, off);
            if (lane == 0) g_bdot[bt] = acc;
        }
    }
    grid_sync();

    // ============ P3: xq = x @ Wuk^T, split-K=8 (128 jobs) ============
    if (cta < 128) {
        int split = cta & 7, mt = (cta >> 3) & 7, nt = cta >> 6;
        int kbase = split * 128, m0 = mt * 128, n0 = nt * 128;
        const __nv_bfloat16* A = g_xb + (size_t)m0 * DIM_ + kbase;
        const __nv_bfloat16* Bm = g_Wuk + (size_t)n0 * DIM_ + kbase;
        float d[2][8][4];
        tile_nt(A, DIM_, Bm, DIM_, 2, dsm, d);
        float* Cp = g_part[split];
        FRAG_LOOP(
            *(float2*)(Cp + (size_t)(m0 + r0) * CV_ + n0 + col)     = make_float2(d[fm][fn][0], d[fm][fn][1]);
            *(float2*)(Cp + (size_t)(m0 + r0 + 8) * CV_ + n0 + col) = make_float2(d[fm][fn][2], d[fm][fn][3]); )
    }
    grid_sync();

    // ============ P4: reduce xq partials -> bf16 ============
    for (int i = cta * 256 + tid; i < 65536; i += NCTA * 256) {
        float4 a = make_float4(0.f, 0.f, 0.f, 0.f);
        #pragma unroll
        for (int s = 0; s < 8; s++) {
            float4 p = ((const float4*)g_part[s])[i];
            a.x += p.x; a.y += p.y; a.z += p.z; a.w += p.w;
        }
        st_bf16x4((__nv_bfloat162*)g_xq, i, a);
    }
    grid_sync();

    // ============ P5: dense logits = (xq.vision + bdot)/32 - 100 (64 jobs) ============
    if (cta < 64) {
        int b = cta >> 4, mt = (cta >> 3) & 1, nt = cta & 7;
        int m0 = mt * 128, n0 = nt * 128;
        const __nv_bfloat16* A = g_xq + (size_t)b * T_ * CV_ + (size_t)m0 * CV_;
        const __nv_bfloat16* Bm = g_visb + (size_t)b * V_ * CV_ + (size_t)n0 * CV_;
        float d[2][8][4];
        tile_nt(A, CV_, Bm, CV_, 4, dsm, d);
        float* L = g_logitD + (size_t)b * T_ * V_;
        FRAG_LOOP(
            float bd0 = g_bdot[b * T_ + m0 + r0];
            float bd1 = g_bdot[b * T_ + m0 + r0 + 8];
            *(float2*)(L + (size_t)(m0 + r0) * V_ + n0 + col) =
                make_float2((d[fm][fn][0] + bd0) * 0.03125f - 100.0f,
                            (d[fm][fn][1] + bd0) * 0.03125f - 100.0f);
            *(float2*)(L + (size_t)(m0 + r0 + 8) * V_ + n0 + col) =
                make_float2((d[fm][fn][2] + bd1) * 0.03125f - 100.0f,
                            (d[fm][fn][3] + bd1) * 0.03125f - 100.0f); )
    }
    grid_sync();

    // ============ P6: per-(b,t) masked (max, sumexp); warp per token ============
    {
        int bt = cta * 8 + wid;
        if (bt < B_ * T_) {
            const float* L = g_logitD + (size_t)bt * V_;
            const unsigned* MT = g_maskT + (size_t)bt * 32;
            float m = -1e30f, s = 0.0f;
            #pragma unroll 4
            for (int k = 0; k < 32; k++) {
                unsigned wd = MT[k];
                if ((wd >> lane) & 1u) ms_comb(m, s, L[k * 32 + lane], 1.0f);
            }
            #pragma unroll
            for (int off = 16; off > 0; off >>= 1) {
                float m2 = __shfl_xor_sync(0xffffffffu, m, off);
                float s2 = __shfl_xor_sync(0xffffffffu, s, off);
                ms_comb(m, s, m2, s2);
            }
            if (lane == 0) g_ms[bt] = make_float2(m, s);
        }
    }
    grid_sync();

    // ============ P7: batch combine + weights w (bf16) + wsum ============
    {
        float* sbM = (float*)dsm;          // [4]
        float* sbS = (float*)dsm + 4;
        if (wid < 4) {
            float m = -1e30f, s = 0.0f;
            for (int j = lane; j < T_; j += 32) {
                float2 v = g_ms[wid * T_ + j];
                ms_comb(m, s, v.x, v.y);
            }
            #pragma unroll
            for (int off = 16; off > 0; off >>= 1) {
                float m2 = __shfl_xor_sync(0xffffffffu, m, off);
                float s2 = __shfl_xor_sync(0xffffffffu, s, off);
                ms_comb(m, s, m2, s2);
            }
            if (lane == 0) { sbM[wid] = m; sbS[wid] = s; }
        }
        __syncthreads();
        int bt = cta * 8 + wid;
        if (bt < B_ * T_) {
            int b = bt >> 8;
            float M = sbM[b], inv = 1.0f / sbS[b];
            const float* L = g_logitD + (size_t)bt * V_;
            const unsigned* MT = g_maskT + (size_t)bt * 32;
            __nv_bfloat16* W = g_w + (size_t)bt * V_;
            float wsum = 0.0f;
            #pragma unroll 4
            for (int k = 0; k < 32; k++) {
                unsigned wd = MT[k];
                float w = 0.0f;
                if ((wd >> lane) & 1u) w = __expf(L[k * 32 + lane] - M) * inv;
                W[k * 32 + lane] = __float2bfloat16(w);
                wsum += w;
            }
            #pragma unroll
            for (int off = 16; off > 0; off >>= 1)
                wsum += __shfl_xor_sync(0xffffffffu, wsum, off);
            if (lane == 0) g_wsum[bt] = wsum;
        }
    }
    grid_sync();

    // ============ P8: agg = w @ vision, split-K=8 (128 jobs) ============
    if (cta < 128) {
        int b = cta & 3, split = (cta >> 2) & 7, mt = (cta >> 5) & 1, nt = cta >> 6;
        int kbase = split * 128, m0 = mt * 128, n0 = nt * 128;
        const __nv_bfloat16* A = g_w + (size_t)b * T_ * V_ + (size_t)m0 * V_ + kbase;
        const __nv_bfloat16* Bm = g_visb + (size_t)b * V_ * CV_ + (size_t)kbase * CV_ + n0;
        float d[2][8][4];
        tile_tn(A, V_, Bm, CV_, 2, dsm, d);
        float* Cp = g_part[split] + (size_t)b * T_ * CV_;
        FRAG_LOOP(
            *(float2*)(Cp + (size_t)(m0 + r0) * CV_ + n0 + col)     = make_float2(d[fm][fn][0], d[fm][fn][1]);
            *(float2*)(Cp + (size_t)(m0 + r0 + 8) * CV_ + n0 + col) = make_float2(d[fm][fn][2], d[fm][fn][3]); )
    }
    grid_sync();

    // ============ P9: reduce agg partials -> bf16 ============
    for (int i = cta * 256 + tid; i < 65536; i += NCTA * 256) {
        float4 a = make_float4(0.f, 0.f, 0.f, 0.f);
        #pragma unroll
        for (int s = 0; s < 8; s++) {
            float4 p = ((const float4*)g_part[s])[i];
            a.x += p.x; a.y += p.y; a.z += p.z; a.w += p.w;
        }
        st_bf16x4((__nv_bfloat162*)g_agg, i, a);
    }
    grid_sync();

    // ============ P10: out = x + agg @ Wuv + wsum*buv (64 jobs) ============
    if (cta < 64) {
        int mt = cta >> 3, nt = cta & 7;
        int m0 = mt * 128, n0 = nt * 128;
        const __nv_bfloat16* A = g_agg + (size_t)m0 * CV_;
        const __nv_bfloat16* Bm = g_Wuv + n0;
        float d[2][8][4];
        tile_tn(A, CV_, Bm, DIM_, 4, dsm, d);
        FRAG_LOOP(
            int r = m0 + r0;
            float ws0 = g_wsum[r], ws1 = g_wsum[r + 8];
            float b0 = g_buv[n0 + col], b1 = g_buv[n0 + col + 1];
            float2 x0 = *(const float2*)(x + (size_t)r * DIM_ + n0 + col);
            float2 x1 = *(const float2*)(x + (size_t)(r + 8) * DIM_ + n0 + col);
            *(float2*)(out + (size_t)r * DIM_ + n0 + col) =
                make_float2(d[fm][fn][0] + x0.x + ws0 * b0,
                            d[fm][fn][1] + x0.y + ws0 * b1);
            *(float2*)(out + (size_t)(r + 8) * DIM_ + n0 + col) =
                make_float2(d[fm][fn][2] + x1.x + ws1 * b0,
                            d[fm][fn][3] + x1.y + ws1 * b1); )
    }
}

// ---------------------------------------------------------------------------
// Launch: ONE kernel
// ---------------------------------------------------------------------------
extern "C" void kernel_launch(void* const* d_in, const int* in_sizes, int n_in,
                              void* d_out, int out_size)
{
    const float* x      = (const float*)d_in[0];
    const float* vision = (const float*)d_in[1];
    const int*   mask   = (const int*)  d_in[2];
    const float* Wu     = (const float*)d_in[3];
    const float* bu     = (const float*)d_in[4];
    const float* Wk     = (const float*)d_in[5];
    const float* Wv     = (const float*)d_in[6];

    static int init_done = 0;
    if (!init_done) {
        cudaFuncSetAttribute(mega_kernel,
                             cudaFuncAttributeMaxDynamicSharedMemorySize, DSM_BYTES);
        init_done = 1;
    }

    mega_kernel<<<NCTA, 256, DSM_BYTES>>>(x, vision, mask, Wu, bu, Wk, Wv, (float*)d_out);
}

// round 11
// speedup vs baseline: 1.4615x; 1.2574x over previous
#include <cuda_runtime.h>
#include <cuda_bf16.h>
#include <cstdint>
#include <math.h>

#define B_   4
#define T_   256
#define V_   1024
#define DIM_ 1024
#define CV_  256
#define NCTA 148

// ---------------------------------------------------------------------------
// Scratch (static device globals)
// ---------------------------------------------------------------------------
__device__ __nv_bfloat16 g_visb[B_ * V_ * CV_];   // vision bf16
__device__ __nv_bfloat16 g_xb  [B_ * T_ * DIM_]; // x bf16
__device__ __nv_bfloat16 g_Wub [CV_ * DIM_];
__device__ __nv_bfloat16 g_Wkb [DIM_ * DIM_];
__device__ __nv_bfloat16 g_Wvb [DIM_ * DIM_];
__device__ __nv_bfloat16 g_Wuk [CV_ * DIM_];      // Wu@Wk
__device__ __nv_bfloat16 g_Wuv [CV_ * DIM_];      // Wu@Wv
__device__ float         g_part[8][CV_ * DIM_];   // split-K partials
__device__ float         g_buk [DIM_];
__device__ float         g_buv [DIM_];
__device__ float         g_bdot[B_ * T_];
__device__ __nv_bfloat16 g_xq  [B_ * T_ * CV_];
__device__ unsigned      g_maskT [B_ * T_ * (V_ / 32)]; // bit-packed (b,t,v)
__device__ __nv_bfloat16 g_agg [B_ * T_ * CV_];   // unnormalized agg
__device__ float2        g_ms  [B_ * T_];         // per-token (m, s) final
__device__ unsigned      g_bar_cnt;
__device__ unsigned      g_bar_gen;

// ---------------------------------------------------------------------------
// helpers
// ---------------------------------------------------------------------------
__device__ __forceinline__ uint32_t smem_u32(const void* p) {
    uint32_t a;
    asm("{ .reg .u64 t; cvta.to.shared.u64 t, %1; cvt.u32.u64 %0, t; }"
        : "=r"(a) : "l"(p));
    return a;
}
__device__ __forceinline__ void cp_async16(uint32_t dst, const void* src) {
    asm volatile("cp.async.cg.shared.global [%0], [%1], 16;" :: "r"(dst), "l"(src));
}
#define CP_COMMIT() asm volatile("cp.async.commit_group;" ::: "memory")
#define CP_WAIT(n)  asm volatile("cp.async.wait_group %0;" :: "n"(n) : "memory")

__device__ __forceinline__ void ldmatrix_x4(uint32_t* r, uint32_t addr) {
    asm volatile("ldmatrix.sync.aligned.m8n8.x4.shared.b16 {%0,%1,%2,%3}, [%4];"
                 : "=r"(r[0]), "=r"(r[1]), "=r"(r[2]), "=r"(r[3]) : "r"(addr));
}
__device__ __forceinline__ void ldmatrix_x4_trans(uint32_t* r, uint32_t addr) {
    asm volatile("ldmatrix.sync.aligned.m8n8.x4.trans.shared.b16 {%0,%1,%2,%3}, [%4];"
                 : "=r"(r[0]), "=r"(r[1]), "=r"(r[2]), "=r"(r[3]) : "r"(addr));
}
__device__ __forceinline__ void mma16816(float* d, const uint32_t* a, const uint32_t* b) {
    asm volatile(
        "mma.sync.aligned.m16n8k16.row.col.f32.bf16.bf16.f32 "
        "{%0,%1,%2,%3},{%4,%5,%6,%7},{%8,%9},{%0,%1,%2,%3};"
        : "+f"(d[0]), "+f"(d[1]), "+f"(d[2]), "+f"(d[3])
        : "r"(a[0]), "r"(a[1]), "r"(a[2]), "r"(a[3]), "r"(b[0]), "r"(b[1]));
}

// grid-wide barrier (all NCTA CTAs co-resident: 1 CTA/SM)
__device__ __forceinline__ void grid_sync() {
    __syncthreads();
    if (threadIdx.x == 0) {
        volatile unsigned* vgen = &g_bar_gen;
        unsigned gen = *vgen;
        __threadfence();
        if (atomicAdd(&g_bar_cnt, 1u) == NCTA - 1) {
            g_bar_cnt = 0u;
            __threadfence();
            *(volatile unsigned*)&g_bar_gen = gen + 1u;
        } else {
            while (*vgen == gen) { }
        }
        __threadfence();
    }
    __syncthreads();
}

__device__ __forceinline__ void ms_comb(float& m, float& s, float m2, float s2) {
    float nm = fmaxf(m, m2);
    s = s * __expf(m - nm) + s2 * __expf(m2 - nm);
    m = nm;
}
__device__ __forceinline__ void st_bf16x4(__nv_bfloat162* o, int i, float4 a) {
    o[2 * i]     = __floats2bfloat162_rn(a.x, a.y);
    o[2 * i + 1] = __floats2bfloat162_rn(a.z, a.w);
}

// ---------------------------------------------------------------------------
// GEMM tile cores (128x128 tile, 256 threads).
// ---------------------------------------------------------------------------
#define TN_AE 9216                    // A elems per stage (128*72)
#define TN_ST 35840
#define NT_ST 36864

// Flash smem layout (beyond the tile-core region when flash runs)
#define F_VIS_STRIDE 67584            // 128*264*2
#define F_OFF_Q      135168
#define F_OFF_P      143616
#define F_OFF_WRED   147968
#define F_OFF_MSA    148480
#define DSM_BYTES    148736

// TN: C += A[128,K] @ B[K,128]
__device__ __forceinline__ void tile_tn(const __nv_bfloat16* __restrict__ A, int lda,
                                        const __nv_bfloat16* __restrict__ Bm, int ldb,
                                        int nchunks, char* dsm, float d[2][8][4]) {
    const int tid = threadIdx.x, lane = tid & 31, wid = tid >> 5;
    const int warpM = wid & 3, warpN = wid >> 2;
    auto Aadr = [&](int s, int r, int c) { return (__nv_bfloat16*)(dsm + s * TN_ST) + r * 72 + c; };
    auto Badr = [&](int s, int r, int c) { return (__nv_bfloat16*)(dsm + s * TN_ST + TN_AE * 2) + r * 136 + c; };
    #pragma unroll
    for (int i = 0; i < 2; i++)
        #pragma unroll
        for (int j = 0; j < 8; j++)
            #pragma unroll
            for (int q = 0; q < 4; q++) d[i][j][q] = 0.0f;

    auto load_chunk = [&](int c) {
        int buf = c & 1;
        #pragma unroll
        for (int h = 0; h < 4; h++) {
            int p = h * 256 + tid;
            { int row = p >> 3, pc = p & 7;
              cp_async16(smem_u32(Aadr(buf, row, pc * 8)), A + (size_t)row * lda + c * 64 + pc * 8); }
            { int row = p >> 4, pc = p & 15;
              cp_async16(smem_u32(Badr(buf, row, pc * 8)), Bm + (size_t)(c * 64 + row) * ldb + pc * 8); }
        }
        CP_COMMIT();
    };
    load_chunk(0);
    for (int c = 0; c < nchunks; c++) {
        int buf = c & 1;
        if (c + 1 < nchunks) { load_chunk(c + 1); CP_WAIT(1); }
        else                 { CP_WAIT(0); }
        __syncthreads();
        #pragma unroll
        for (int ks = 0; ks < 4; ks++) {
            uint32_t a[2][4];
            #pragma unroll
            for (int fm = 0; fm < 2; fm++) {
                int r  = warpM * 32 + fm * 16 + (lane & 7) + ((lane >> 3) & 1) * 8;
                int kk = ks * 16 + (lane >> 4) * 8;
                ldmatrix_x4(a[fm], smem_u32(Aadr(buf, r, kk)));
            }
            uint32_t b[8][2];
            #pragma unroll
            for (int i = 0; i < 4; i++) {
                int kk = ks * 16 + (lane & 15);
                int nn = warpN * 64 + i * 16 + (lane >> 4) * 8;
                uint32_t tmp[4];
                ldmatrix_x4_trans(tmp, smem_u32(Badr(buf, kk, nn)));
                b[2*i][0]   = tmp[0]; b[2*i][1]   = tmp[1];
                b[2*i+1][0] = tmp[2]; b[2*i+1][1] = tmp[3];
            }
            #pragma unroll
            for (int fm = 0; fm < 2; fm++)
                #pragma unroll
                for (int fn = 0; fn < 8; fn++)
                    mma16816(d[fm][fn], a[fm], b[fn]);
        }
        __syncthreads();
    }
}

// NT: C += A[128,K] @ B[128,K]^T
__device__ __forceinline__ void tile_nt(const __nv_bfloat16* __restrict__ A, int lda,
                                        const __nv_bfloat16* __restrict__ Bm, int ldb,
                                        int nchunks, char* dsm, float d[2][8][4]) {
    const int tid = threadIdx.x, lane = tid & 31, wid = tid >> 5;
    const int warpM = wid & 3, warpN = wid >> 2;
    auto Aadr = [&](int s, int r, int c) { return (__nv_bfloat16*)(dsm + s * NT_ST) + r * 72 + c; };
    auto Badr = [&](int s, int r, int c) { return (__nv_bfloat16*)(dsm + s * NT_ST + TN_AE * 2) + r * 72 + c; };
    #pragma unroll
    for (int i = 0; i < 2; i++)
        #pragma unroll
        for (int j = 0; j < 8; j++)
            #pragma unroll
            for (int q = 0; q < 4; q++) d[i][j][q] = 0.0f;

    auto load_chunk = [&](int c) {
        int buf = c & 1;
        #pragma unroll
        for (int h = 0; h < 4; h++) {
            int p = h * 256 + tid;
            int row = p >> 3, pc = p & 7;
            cp_async16(smem_u32(Aadr(buf, row, pc * 8)), A + (size_t)row * lda + c * 64 + pc * 8);
            cp_async16(smem_u32(Badr(buf, row, pc * 8)), Bm + (size_t)row * ldb + c * 64 + pc * 8);
        }
        CP_COMMIT();
    };
    load_chunk(0);
    for (int c = 0; c < nchunks; c++) {
        int buf = c & 1;
        if (c + 1 < nchunks) { load_chunk(c + 1); CP_WAIT(1); }
        else                 { CP_WAIT(0); }
        __syncthreads();
        #pragma unroll
        for (int ks = 0; ks < 4; ks++) {
            uint32_t a[2][4];
            #pragma unroll
            for (int fm = 0; fm < 2; fm++) {
                int r  = warpM * 32 + fm * 16 + (lane & 7) + ((lane >> 3) & 1) * 8;
                int kk = ks * 16 + (lane >> 4) * 8;
                ldmatrix_x4(a[fm], smem_u32(Aadr(buf, r, kk)));
            }
            uint32_t b[8][2];
            #pragma unroll
            for (int i = 0; i < 4; i++) {
                int r  = warpN * 64 + i * 16 + (lane & 7) + (lane >> 4) * 8;
                int kk = ks * 16 + ((lane >> 3) & 1) * 8;
                uint32_t tmp[4];
                ldmatrix_x4(tmp, smem_u32(Badr(buf, r, kk)));
                b[2*i][0]   = tmp[0]; b[2*i][1]   = tmp[1];
                b[2*i+1][0] = tmp[2]; b[2*i+1][1] = tmp[3];
            }
            #pragma unroll
            for (int fm = 0; fm < 2; fm++)
                #pragma unroll
                for (int fn = 0; fn < 8; fn++)
                    mma16816(d[fm][fn], a[fm], b[fn]);
        }
        __syncthreads();
    }
}

#define FRAG_LOOP(...) \
    { const int lane_ = threadIdx.x & 31, wid_ = threadIdx.x >> 5; \
      const int warpM_ = wid_ & 3, warpN_ = wid_ >> 2; \
      _Pragma("unroll") for (int fm = 0; fm < 2; fm++) \
      _Pragma("unroll") for (int fn = 0; fn < 8; fn++) { \
          int r0  = warpM_ * 32 + fm * 16 + (lane_ >> 2); \
          int col = warpN_ * 64 + fn * 8 + 2 * (lane_ & 3); \
          __VA_ARGS__ } }

// ---------------------------------------------------------------------------
// The persistent mega-kernel
// ---------------------------------------------------------------------------
extern "C" __global__ void __launch_bounds__(256)
mega_kernel(const float* __restrict__ x, const float* __restrict__ vision,
            const int* __restrict__ mask, const float* __restrict__ Wu,
            const float* __restrict__ bu, const float* __restrict__ Wk,
            const float* __restrict__ Wv, float* __restrict__ out)
{
    extern __shared__ char dsm[];
    const int cta = blockIdx.x, tid = threadIdx.x;
    const int lane = tid & 31, wid = tid >> 5;

    // ============ P0: converts + maskT bitpack + bias fold ============
    if (cta < 116) {
        const int stride = 116 * 256;
        int base = cta * 256 + tid;
        for (int i = base; i < B_*V_*CV_/4; i += stride) {
            float4 v = ((const float4*)vision)[i];
            st_bf16x4((__nv_bfloat162*)g_visb, i, v);
        }
        for (int i = base; i < CV_*DIM_/4; i += stride) {
            float4 v = ((const float4*)Wu)[i];
            st_bf16x4((__nv_bfloat162*)g_Wub, i, v);
        }
        for (int i = base; i < DIM_*DIM_/4; i += stride) {
            float4 v = ((const float4*)Wk)[i];
            st_bf16x4((__nv_bfloat162*)g_Wkb, i, v);
        }
        for (int i = base; i < DIM_*DIM_/4; i += stride) {
            float4 v = ((const float4*)Wv)[i];
            st_bf16x4((__nv_bfloat162*)g_Wvb, i, v);
        }
        for (int i = base; i < B_*T_*DIM_/4; i += stride) {
            float4 v = ((const float4*)x)[i];
            st_bf16x4((__nv_bfloat162*)g_xb, i, v);
        }
        // maskT bitpack: tiles of 32 v x 256 t
        int* tile = (int*)dsm;   // [32][257]
        for (int job = cta; job < 128; job += 116) {
            int b = job >> 5, v0 = (job & 31) * 32;
            const int* mp = mask + (size_t)b * V_ * T_;
            __syncthreads();
            #pragma unroll
            for (int vr = 0; vr < 32; vr++)
                tile[vr * 257 + tid] = mp[(size_t)(v0 + vr) * T_ + tid];
            __syncthreads();
            unsigned word = 0;
            #pragma unroll
            for (int vr = 0; vr < 32; vr++)
                word |= (tile[vr * 257 + tid] != 0 ? 1u : 0u) << vr;
            g_maskT[((size_t)b * T_ + tid) * 32 + (job & 31)] = word;
        }
    } else {
        // bias fold: 32 CTAs, each 64 outputs, 4-way K split
        int idx = cta - 116;
        int kv = idx & 1, n0b = (idx >> 1) * 64;
        const float* W = kv ? Wv : Wk;
        int tx = tid & 63, ty = tid >> 6;
        float acc = 0.0f;
        int c0 = ty * 256;
        #pragma unroll 8
        for (int c = c0; c < c0 + 256; c++)
            acc = fmaf(bu[c], W[(size_t)c * DIM_ + n0b + tx], acc);
        float* sp = (float*)dsm;
        sp[ty * 64 + tx] = acc;
        __syncthreads();
        if (ty == 0)
            (kv ? g_buv : g_buk)[n0b + tx] = sp[tx] + sp[64+tx] + sp[128+tx] + sp[192+tx];
    }
    grid_sync();

    // ============ P1: Wuk/Wuv = Wu @ Wk/Wv, split-K=4 (128 jobs) ============
    if (cta < 128) {
        int kv = cta & 1, split = (cta >> 1) & 3, mt = (cta >> 3) & 1, nt = cta >> 4;
        int kbase = split * 256, m0 = mt * 128, n0 = nt * 128;
        const __nv_bfloat16* A = g_Wub + (size_t)m0 * DIM_ + kbase;
        const __nv_bfloat16* Bm = (kv ? g_Wvb : g_Wkb) + (size_t)kbase * DIM_ + n0;
        float d[2][8][4];
        tile_tn(A, DIM_, Bm, DIM_, 4, dsm, d);
        float* Cp = g_part[kv * 4 + split];
        FRAG_LOOP(
            *(float2*)(Cp + (size_t)(m0 + r0) * DIM_ + n0 + col)     = make_float2(d[fm][fn][0], d[fm][fn][1]);
            *(float2*)(Cp + (size_t)(m0 + r0 + 8) * DIM_ + n0 + col) = make_float2(d[fm][fn][2], d[fm][fn][3]); )
    }
    grid_sync();

    // ============ P2: reduce Wuk/Wuv -> bf16 ; bdot = buk . x[t] ============
    for (int i = cta * 256 + tid; i < 131072; i += NCTA * 256) {
        int kv = i >> 16, j = i & 65535;
        float4 a = make_float4(0.f, 0.f, 0.f, 0.f);
        #pragma unroll
        for (int s = 0; s < 4; s++) {
            float4 p = ((const float4*)g_part[kv * 4 + s])[j];
            a.x += p.x; a.y += p.y; a.z += p.z; a.w += p.w;
        }
        st_bf16x4((__nv_bfloat162*)(kv ? g_Wuv : g_Wuk), j, a);
    }
    {
        int bt = cta * 8 + wid;
        if (bt < B_ * T_) {
            const float* xr = x + (size_t)bt * DIM_;
            float acc = 0.0f;
            #pragma unroll
            for (int k = 0; k < 32; k++)
                acc = fmaf(xr[k * 32 + lane], g_buk[k * 32 + lane], acc);
            #pragma unroll
            for (int off = 16; off > 0; off >>= 1)
                acc += __shfl_down_sync(0xffffffffu, acc, off);
            if (lane == 0) g_bdot[bt] = acc;
        }
    }
    grid_sync();

    // ============ P3: xq = x @ Wuk^T, split-K=8 (128 jobs) ============
    if (cta < 128) {
        int split = cta & 7, mt = (cta >> 3) & 7, nt = cta >> 6;
        int kbase = split * 128, m0 = mt * 128, n0 = nt * 128;
        const __nv_bfloat16* A = g_xb + (size_t)m0 * DIM_ + kbase;
        const __nv_bfloat16* Bm = g_Wuk + (size_t)n0 * DIM_ + kbase;
        float d[2][8][4];
        tile_nt(A, DIM_, Bm, DIM_, 2, dsm, d);
        float* Cp = g_part[split];
        FRAG_LOOP(
            *(float2*)(Cp + (size_t)(m0 + r0) * CV_ + n0 + col)     = make_float2(d[fm][fn][0], d[fm][fn][1]);
            *(float2*)(Cp + (size_t)(m0 + r0 + 8) * CV_ + n0 + col) = make_float2(d[fm][fn][2], d[fm][fn][3]); )
    }
    grid_sync();

    // ============ P4: reduce xq partials -> bf16 ============
    for (int i = cta * 256 + tid; i < 65536; i += NCTA * 256) {
        float4 a = make_float4(0.f, 0.f, 0.f, 0.f);
        #pragma unroll
        for (int s = 0; s < 8; s++) {
            float4 p = ((const float4*)g_part[s])[i];
            a.x += p.x; a.y += p.y; a.z += p.z; a.w += p.w;
        }
        st_bf16x4((__nv_bfloat162*)g_xq, i, a);
    }
    grid_sync();

    // ============ P5: FLASH — logits + online masked softmax + agg ============
    // 64 jobs: b = cta>>4, 16 tokens each. agg_un = sum_v e^{l-m_t} * vision[v]
    if (cta < 64) {
        const int b = cta >> 4, t0 = (cta & 15) * 16;
        char* Qs = dsm + F_OFF_Q;
        char* Ps = dsm + F_OFF_P;
        float* wred  = (float*)(dsm + F_OFF_WRED);   // [16][8]
        float* m_arr = (float*)(dsm + F_OFF_MSA);    // 16
        float* s_arr = m_arr + 16;
        float* f_arr = s_arr + 16;
        float* bd    = f_arr + 16;
        const int w8 = wid;
        const int r_lo = lane >> 2, r_hi = r_lo + 8;

        if (tid < 16) {
            m_arr[tid] = -1e30f; s_arr[tid] = 0.0f;
            bd[tid] = g_bdot[b * T_ + t0 + tid];
        }
        // G0: Q (xq rows) + Vis chunk 0
        #pragma unroll
        for (int h = 0; h < 2; h++) {
            int p = h * 256 + tid; int row = p >> 5, pc = p & 31;
            cp_async16(smem_u32(Qs + (row * 264 + pc * 8) * 2),
                       g_xq + ((size_t)(b * T_ + t0 + row)) * CV_ + pc * 8);
        }
        #pragma unroll
        for (int h = 0; h < 16; h++) {
            int p = h * 256 + tid; int row = p >> 5, pc = p & 31;
            cp_async16(smem_u32(dsm + (row * 264 + pc * 8) * 2),
                       g_visb + ((size_t)(b * V_ + row)) * CV_ + pc * 8);
        }
        CP_COMMIT();

        float d2[4][4];
        #pragma unroll
        for (int i = 0; i < 4; i++)
            #pragma unroll
            for (int q = 0; q < 4; q++) d2[i][q] = 0.0f;

        for (int c = 0; c < 8; c++) {
            int buf = c & 1;
            if (c + 1 < 8) {
                int nbuf = (c + 1) & 1;
                #pragma unroll
                for (int h = 0; h < 16; h++) {
                    int p = h * 256 + tid; int row = p >> 5, pc = p & 31;
                    cp_async16(smem_u32(dsm + nbuf * F_VIS_STRIDE + (row * 264 + pc * 8) * 2),
                               g_visb + ((size_t)(b * V_ + (c + 1) * 128 + row)) * CV_ + pc * 8);
                }
                CP_COMMIT(); CP_WAIT(1);
            } else CP_WAIT(0);
            __syncthreads();
            char* VIS = dsm + buf * F_VIS_STRIDE;

            // --- mma1: logits tile [16 x 128] = Q[16,256] @ Vis[128,256]^T ---
            float d1[2][4];
            #pragma unroll
            for (int i = 0; i < 2; i++)
                #pragma unroll
                for (int q = 0; q < 4; q++) d1[i][q] = 0.0f;
            #pragma unroll
            for (int ks = 0; ks < 16; ks++) {
                uint32_t aF[4];
                int rA = lane & 15, kk = ks * 16 + (lane >> 4) * 8;
                ldmatrix_x4(aF, smem_u32(Qs + (rA * 264 + kk) * 2));
                int rb = w8 * 16 + (lane & 7) + (lane >> 4) * 8;
                int kkb = ks * 16 + ((lane >> 3) & 1) * 8;
                uint32_t t4[4];
                ldmatrix_x4(t4, smem_u32(VIS + (rb * 264 + kkb) * 2));
                uint32_t b0[2] = {t4[0], t4[1]}, b1[2] = {t4[2], t4[3]};
                mma16816(d1[0], aF, b0);
                mma16816(d1[1], aF, b1);
            }

            // --- masked online softmax stats ---
            int v0 = c * 128;
            unsigned wlo = g_maskT[((size_t)(b * T_ + t0 + r_lo)) * 32 + ((v0 + w8 * 16) >> 5)];
            unsigned whi = g_maskT[((size_t)(b * T_ + t0 + r_hi)) * 32 + ((v0 + w8 * 16) >> 5)];
            float lv[2][4]; bool mk[2][4];
            float mx0 = -1e30f, mx1 = -1e30f;
            #pragma unroll
            for (int fn = 0; fn < 2; fn++) {
                int cb = w8 * 16 + fn * 8 + 2 * (lane & 3);
                #pragma unroll
                for (int j = 0; j < 4; j++) {
                    int cc = cb + (j & 1);
                    bool hi = (j >> 1);
                    unsigned word = hi ? whi : wlo;
                    bool m = (word >> (cc & 31)) & 1u;
                    float l = (d1[fn][j] + bd[hi ? r_hi : r_lo]) * 0.03125f;
                    lv[fn][j] = l; mk[fn][j] = m;
                    if (m) { if (hi) mx1 = fmaxf(mx1, l); else mx0 = fmaxf(mx0, l); }
                }
            }
            #pragma unroll
            for (int off = 1; off <= 2; off <<= 1) {
                mx0 = fmaxf(mx0, __shfl_xor_sync(0xffffffffu, mx0, off));
                mx1 = fmaxf(mx1, __shfl_xor_sync(0xffffffffu, mx1, off));
            }
            if ((lane & 3) == 0) { wred[r_lo * 8 + w8] = mx0; wred[r_hi * 8 + w8] = mx1; }
            __syncthreads();
            if (tid < 16) {
                float tm = wred[tid * 8];
                #pragma unroll
                for (int k = 1; k < 8; k++) tm = fmaxf(tm, wred[tid * 8 + k]);
                float mo = m_arr[tid];
                float mn = fmaxf(mo, tm);
                f_arr[tid] = __expf(mo - mn);
                s_arr[tid] *= f_arr[tid];
                m_arr[tid] = mn;
            }
            __syncthreads();
            float mlo = m_arr[r_lo], mhi = m_arr[r_hi];
            float se0 = 0.0f, se1 = 0.0f;
            #pragma unroll
            for (int fn = 0; fn < 2; fn++) {
                int cb = w8 * 16 + fn * 8 + 2 * (lane & 3);
                float p0 = mk[fn][0] ? __expf(lv[fn][0] - mlo) : 0.0f;
                float p1 = mk[fn][1] ? __expf(lv[fn][1] - mlo) : 0.0f;
                float p2 = mk[fn][2] ? __expf(lv[fn][2] - mhi) : 0.0f;
                float p3 = mk[fn][3] ? __expf(lv[fn][3] - mhi) : 0.0f;
                se0 += p0 + p1; se1 += p2 + p3;
                *(__nv_bfloat162*)(Ps + (r_lo * 136 + cb) * 2) = __floats2bfloat162_rn(p0, p1);
                *(__nv_bfloat162*)(Ps + (r_hi * 136 + cb) * 2) = __floats2bfloat162_rn(p2, p3);
            }
            #pragma unroll
            for (int off = 1; off <= 2; off <<= 1) {
                se0 += __shfl_xor_sync(0xffffffffu, se0, off);
                se1 += __shfl_xor_sync(0xffffffffu, se1, off);
            }
            if ((lane & 3) == 0) { wred[r_lo * 8 + w8] = se0; wred[r_hi * 8 + w8] = se1; }
            // rescale accumulator
            float f0 = f_arr[r_lo], f1 = f_arr[r_hi];
            #pragma unroll
            for (int fn = 0; fn < 4; fn++) {
                d2[fn][0] *= f0; d2[fn][1] *= f0;
                d2[fn][2] *= f1; d2[fn][3] *= f1;
            }
            __syncthreads();
            if (tid < 16) {
                float ss = 0.0f;
                #pragma unroll
                for (int k = 0; k < 8; k++) ss += wred[tid * 8 + k];
                s_arr[tid] += ss;
            }

            // --- mma2: acc[16,256] += P[16,128] @ Vis[128,256] ---
            #pragma unroll
            for (int ks = 0; ks < 8; ks++) {
                uint32_t aF[4];
                int rA = lane & 15, kk = ks * 16 + (lane >> 4) * 8;
                ldmatrix_x4(aF, smem_u32(Ps + (rA * 136 + kk) * 2));
                #pragma unroll
                for (int i = 0; i < 2; i++) {
                    int kkb = ks * 16 + (lane & 15);
                    int nn = w8 * 32 + i * 16 + (lane >> 4) * 8;
                    uint32_t t4[4];
                    ldmatrix_x4_trans(t4, smem_u32(VIS + (kkb * 264 + nn) * 2));
                    uint32_t b0[2] = {t4[0], t4[1]}, b1[2] = {t4[2], t4[3]};
                    mma16816(d2[2*i], aF, b0);
                    mma16816(d2[2*i+1], aF, b1);
                }
            }
            __syncthreads();
        }
        // write agg (bf16) + per-token (m, s)
        #pragma unroll
        for (int fn = 0; fn < 4; fn++) {
            int cb = w8 * 32 + fn * 8 + 2 * (lane & 3);
            *(__nv_bfloat162*)(g_agg + ((size_t)(b * T_ + t0 + r_lo)) * CV_ + cb) =
                __floats2bfloat162_rn(d2[fn][0], d2[fn][1]);
            *(__nv_bfloat162*)(g_agg + ((size_t)(b * T_ + t0 + r_hi)) * CV_ + cb) =
                __floats2bfloat162_rn(d2[fn][2], d2[fn][3]);
        }
        if (tid < 16) g_ms[b * T_ + t0 + tid] = make_float2(m_arr[tid], s_arr[tid]);
    }
    grid_sync();

    // ============ P6: out = x + scale*(agg @ Wuv) + wsum*buv (64 jobs) ============
    if (cta < 64) {
        int mt = cta >> 3, nt = cta & 7;
        int m0 = mt * 128, n0 = nt * 128, b = m0 >> 8;
        // per-batch (M, S) reduce over 256 tokens
        float* rm = (float*)(dsm + 73728);
        float* rs = rm + 256;
        float2 v = g_ms[b * T_ + tid];
        rm[tid] = v.x; rs[tid] = v.y;
        __syncthreads();
        for (int st = 128; st > 0; st >>= 1) {
            if (tid < st) {
                float mm = rm[tid], ssv = rs[tid];
                ms_comb(mm, ssv, rm[tid + st], rs[tid + st]);
                rm[tid] = mm; rs[tid] = ssv;
            }
            __syncthreads();
        }
        float Mb = rm[0], Sb = rs[0];
        __syncthreads();

        float d[2][8][4];
        tile_tn(g_agg + (size_t)m0 * CV_, CV_, g_Wuv + n0, DIM_, 4, dsm, d);
        FRAG_LOOP(
            int r = m0 + r0;
            float2 ms0 = g_ms[r];
            float2 ms1 = g_ms[r + 8];
            float sc0 = __expf(ms0.x - Mb) / Sb;
            float sc1 = __expf(ms1.x - Mb) / Sb;
            float ws0 = ms0.y * sc0;
            float ws1 = ms1.y * sc1;
            float b0v = g_buv[n0 + col], b1v = g_buv[n0 + col + 1];
            float2 x0 = *(const float2*)(x + (size_t)r * DIM_ + n0 + col);
            float2 x1 = *(const float2*)(x + (size_t)(r + 8) * DIM_ + n0 + col);
            *(float2*)(out + (size_t)r * DIM_ + n0 + col) =
                make_float2(sc0 * d[fm][fn][0] + x0.x + ws0 * b0v,
                            sc0 * d[fm][fn][1] + x0.y + ws0 * b1v);
            *(float2*)(out + (size_t)(r + 8) * DIM_ + n0 + col) =
                make_float2(sc1 * d[fm][fn][2] + x1.x + ws1 * b0v,
                            sc1 * d[fm][fn][3] + x1.y + ws1 * b1v); )
    }
}

// ---------------------------------------------------------------------------
// Launch: ONE kernel
// ---------------------------------------------------------------------------
extern "C" void kernel_launch(void* const* d_in, const int* in_sizes, int n_in,
                              void* d_out, int out_size)
{
    const float* x      = (const float*)d_in[0];
    const float* vision = (const float*)d_in[1];
    const int*   mask   = (const int*)  d_in[2];
    const float* Wu     = (const float*)d_in[3];
    const float* bu     = (const float*)d_in[4];
    const float* Wk     = (const float*)d_in[5];
    const float* Wv     = (const float*)d_in[6];

    static int init_done = 0;
    if (!init_done) {
        cudaFuncSetAttribute(mega_kernel,
                             cudaFuncAttributeMaxDynamicSharedMemorySize, DSM_BYTES);
        init_done = 1;
    }

    mega_kernel<<<NCTA, 256, DSM_BYTES>>>(x, vision, mask, Wu, bu, Wk, Wv, (float*)d_out);
}

// round 12
// speedup vs baseline: 1.6114x; 1.1026x over previous
#include <cuda_runtime.h>
#include <cuda_bf16.h>
#include <cstdint>
#include <math.h>

#define B_   4
#define T_   256
#define V_   1024
#define DIM_ 1024
#define CV_  256
#define NCTA 148

// ---------------------------------------------------------------------------
// Scratch (static device globals)
// ---------------------------------------------------------------------------
__device__ __nv_bfloat16 g_visb[B_ * V_ * CV_];   // vision bf16
__device__ __nv_bfloat16 g_xb  [B_ * T_ * DIM_]; // x bf16
__device__ __nv_bfloat16 g_Wub [CV_ * DIM_];
__device__ __nv_bfloat16 g_Wkb [DIM_ * DIM_];
__device__ __nv_bfloat16 g_Wvb [DIM_ * DIM_];
__device__ __nv_bfloat16 g_Wuk [CV_ * DIM_];      // Wu@Wk
__device__ __nv_bfloat16 g_Wuv [CV_ * DIM_];      // Wu@Wv
__device__ float         g_part[8][CV_ * DIM_];   // split-K partials
__device__ float         g_buk [DIM_];
__device__ float         g_buv [DIM_];
__device__ unsigned      g_maskT [B_ * T_ * (V_ / 32)]; // bit-packed (b,t,v)
__device__ float         g_aggp[2][B_ * T_ * CV_];// flash V-half partial agg (fp32)
__device__ float2        g_msp [2][B_ * T_];      // flash V-half partial (m,s)
__device__ __nv_bfloat16 g_agg [B_ * T_ * CV_];   // merged unnormalized agg
__device__ float2        g_ms  [B_ * T_];         // merged per-token (m, s)
__device__ unsigned      g_bar_cnt;
__device__ unsigned      g_bar_gen;

// ---------------------------------------------------------------------------
// helpers
// ---------------------------------------------------------------------------
__device__ __forceinline__ uint32_t smem_u32(const void* p) {
    uint32_t a;
    asm("{ .reg .u64 t; cvta.to.shared.u64 t, %1; cvt.u32.u64 %0, t; }"
        : "=r"(a) : "l"(p));
    return a;
}
__device__ __forceinline__ void cp_async16(uint32_t dst, const void* src) {
    asm volatile("cp.async.cg.shared.global [%0], [%1], 16;" :: "r"(dst), "l"(src));
}
#define CP_COMMIT() asm volatile("cp.async.commit_group;" ::: "memory")
#define CP_WAIT(n)  asm volatile("cp.async.wait_group %0;" :: "n"(n) : "memory")

__device__ __forceinline__ void ldmatrix_x4(uint32_t* r, uint32_t addr) {
    asm volatile("ldmatrix.sync.aligned.m8n8.x4.shared.b16 {%0,%1,%2,%3}, [%4];"
                 : "=r"(r[0]), "=r"(r[1]), "=r"(r[2]), "=r"(r[3]) : "r"(addr));
}
__device__ __forceinline__ void ldmatrix_x4_trans(uint32_t* r, uint32_t addr) {
    asm volatile("ldmatrix.sync.aligned.m8n8.x4.trans.shared.b16 {%0,%1,%2,%3}, [%4];"
                 : "=r"(r[0]), "=r"(r[1]), "=r"(r[2]), "=r"(r[3]) : "r"(addr));
}
__device__ __forceinline__ void mma16816(float* d, const uint32_t* a, const uint32_t* b) {
    asm volatile(
        "mma.sync.aligned.m16n8k16.row.col.f32.bf16.bf16.f32 "
        "{%0,%1,%2,%3},{%4,%5,%6,%7},{%8,%9},{%0,%1,%2,%3};"
        : "+f"(d[0]), "+f"(d[1]), "+f"(d[2]), "+f"(d[3])
        : "r"(a[0]), "r"(a[1]), "r"(a[2]), "r"(a[3]), "r"(b[0]), "r"(b[1]));
}

// grid-wide barrier (all NCTA CTAs co-resident: 1 CTA/SM)
__device__ __forceinline__ void grid_sync() {
    __syncthreads();
    if (threadIdx.x == 0) {
        volatile unsigned* vgen = &g_bar_gen;
        unsigned gen = *vgen;
        __threadfence();
        if (atomicAdd(&g_bar_cnt, 1u) == NCTA - 1) {
            g_bar_cnt = 0u;
            __threadfence();
            *(volatile unsigned*)&g_bar_gen = gen + 1u;
        } else {
            while (*vgen == gen) { }
        }
        __threadfence();
    }
    __syncthreads();
}

__device__ __forceinline__ void ms_comb(float& m, float& s, float m2, float s2) {
    float nm = fmaxf(m, m2);
    s = s * __expf(m - nm) + s2 * __expf(m2 - nm);
    m = nm;
}
__device__ __forceinline__ void st_bf16x4(__nv_bfloat162* o, int i, float4 a) {
    o[2 * i]     = __floats2bfloat162_rn(a.x, a.y);
    o[2 * i + 1] = __floats2bfloat162_rn(a.z, a.w);
}

// ---------------------------------------------------------------------------
// GEMM tile cores (128x128 tile, 256 threads).
// ---------------------------------------------------------------------------
#define TN_AE 9216                    // A elems per stage (128*72)
#define TN_ST 35840
#define NT_ST 36864

// Flash smem layout
#define F_VIS_STRIDE 67584            // 128*264*2
#define F_OFF_Q      135168
#define F_OFF_P      143616
#define F_OFF_WRED   147968
#define F_OFF_MSA    148480
#define DSM_BYTES    148736

// TN: C += A[128,K] @ B[K,128]
__device__ __forceinline__ void tile_tn(const __nv_bfloat16* __restrict__ A, int lda,
                                        const __nv_bfloat16* __restrict__ Bm, int ldb,
                                        int nchunks, char* dsm, float d[2][8][4]) {
    const int tid = threadIdx.x, lane = tid & 31, wid = tid >> 5;
    const int warpM = wid & 3, warpN = wid >> 2;
    auto Aadr = [&](int s, int r, int c) { return (__nv_bfloat16*)(dsm + s * TN_ST) + r * 72 + c; };
    auto Badr = [&](int s, int r, int c) { return (__nv_bfloat16*)(dsm + s * TN_ST + TN_AE * 2) + r * 136 + c; };
    #pragma unroll
    for (int i = 0; i < 2; i++)
        #pragma unroll
        for (int j = 0; j < 8; j++)
            #pragma unroll
            for (int q = 0; q < 4; q++) d[i][j][q] = 0.0f;

    auto load_chunk = [&](int c) {
        int buf = c & 1;
        #pragma unroll
        for (int h = 0; h < 4; h++) {
            int p = h * 256 + tid;
            { int row = p >> 3, pc = p & 7;
              cp_async16(smem_u32(Aadr(buf, row, pc * 8)), A + (size_t)row * lda + c * 64 + pc * 8); }
            { int row = p >> 4, pc = p & 15;
              cp_async16(smem_u32(Badr(buf, row, pc * 8)), Bm + (size_t)(c * 64 + row) * ldb + pc * 8); }
        }
        CP_COMMIT();
    };
    load_chunk(0);
    for (int c = 0; c < nchunks; c++) {
        int buf = c & 1;
        if (c + 1 < nchunks) { load_chunk(c + 1); CP_WAIT(1); }
        else                 { CP_WAIT(0); }
        __syncthreads();
        #pragma unroll
        for (int ks = 0; ks < 4; ks++) {
            uint32_t a[2][4];
            #pragma unroll
            for (int fm = 0; fm < 2; fm++) {
                int r  = warpM * 32 + fm * 16 + (lane & 7) + ((lane >> 3) & 1) * 8;
                int kk = ks * 16 + (lane >> 4) * 8;
                ldmatrix_x4(a[fm], smem_u32(Aadr(buf, r, kk)));
            }
            uint32_t b[8][2];
            #pragma unroll
            for (int i = 0; i < 4; i++) {
                int kk = ks * 16 + (lane & 15);
                int nn = warpN * 64 + i * 16 + (lane >> 4) * 8;
                uint32_t tmp[4];
                ldmatrix_x4_trans(tmp, smem_u32(Badr(buf, kk, nn)));
                b[2*i][0]   = tmp[0]; b[2*i][1]   = tmp[1];
                b[2*i+1][0] = tmp[2]; b[2*i+1][1] = tmp[3];
            }
            #pragma unroll
            for (int fm = 0; fm < 2; fm++)
                #pragma unroll
                for (int fn = 0; fn < 8; fn++)
                    mma16816(d[fm][fn], a[fm], b[fn]);
        }
        __syncthreads();
    }
}

// NT: C += A[128,K] @ B[128,K]^T
__device__ __forceinline__ void tile_nt(const __nv_bfloat16* __restrict__ A, int lda,
                                        const __nv_bfloat16* __restrict__ Bm, int ldb,
                                        int nchunks, char* dsm, float d[2][8][4]) {
    const int tid = threadIdx.x, lane = tid & 31, wid = tid >> 5;
    const int warpM = wid & 3, warpN = wid >> 2;
    auto Aadr = [&](int s, int r, int c) { return (__nv_bfloat16*)(dsm + s * NT_ST) + r * 72 + c; };
    auto Badr = [&](int s, int r, int c) { return (__nv_bfloat16*)(dsm + s * NT_ST + TN_AE * 2) + r * 72 + c; };
    #pragma unroll
    for (int i = 0; i < 2; i++)
        #pragma unroll
        for (int j = 0; j < 8; j++)
            #pragma unroll
            for (int q = 0; q < 4; q++) d[i][j][q] = 0.0f;

    auto load_chunk = [&](int c) {
        int buf = c & 1;
        #pragma unroll
        for (int h = 0; h < 4; h++) {
            int p = h * 256 + tid;
            int row = p >> 3, pc = p & 7;
            cp_async16(smem_u32(Aadr(buf, row, pc * 8)), A + (size_t)row * lda + c * 64 + pc * 8);
            cp_async16(smem_u32(Badr(buf, row, pc * 8)), Bm + (size_t)row * ldb + c * 64 + pc * 8);
        }
        CP_COMMIT();
    };
    load_chunk(0);
    for (int c = 0; c < nchunks; c++) {
        int buf = c & 1;
        if (c + 1 < nchunks) { load_chunk(c + 1); CP_WAIT(1); }
        else                 { CP_WAIT(0); }
        __syncthreads();
        #pragma unroll
        for (int ks = 0; ks < 4; ks++) {
            uint32_t a[2][4];
            #pragma unroll
            for (int fm = 0; fm < 2; fm++) {
                int r  = warpM * 32 + fm * 16 + (lane & 7) + ((lane >> 3) & 1) * 8;
                int kk = ks * 16 + (lane >> 4) * 8;
                ldmatrix_x4(a[fm], smem_u32(Aadr(buf, r, kk)));
            }
            uint32_t b[8][2];
            #pragma unroll
            for (int i = 0; i < 4; i++) {
                int r  = warpN * 64 + i * 16 + (lane & 7) + (lane >> 4) * 8;
                int kk = ks * 16 + ((lane >> 3) & 1) * 8;
                uint32_t tmp[4];
                ldmatrix_x4(tmp, smem_u32(Badr(buf, r, kk)));
                b[2*i][0]   = tmp[0]; b[2*i][1]   = tmp[1];
                b[2*i+1][0] = tmp[2]; b[2*i+1][1] = tmp[3];
            }
            #pragma unroll
            for (int fm = 0; fm < 2; fm++)
                #pragma unroll
                for (int fn = 0; fn < 8; fn++)
                    mma16816(d[fm][fn], a[fm], b[fn]);
        }
        __syncthreads();
    }
}

#define FRAG_LOOP(...) \
    { const int lane_ = threadIdx.x & 31, wid_ = threadIdx.x >> 5; \
      const int warpM_ = wid_ & 3, warpN_ = wid_ >> 2; \
      _Pragma("unroll") for (int fm = 0; fm < 2; fm++) \
      _Pragma("unroll") for (int fn = 0; fn < 8; fn++) { \
          int r0  = warpM_ * 32 + fm * 16 + (lane_ >> 2); \
          int col = warpN_ * 64 + fn * 8 + 2 * (lane_ & 3); \
          __VA_ARGS__ } }

// ---------------------------------------------------------------------------
// The persistent mega-kernel
// ---------------------------------------------------------------------------
extern "C" __global__ void __launch_bounds__(256)
mega_kernel(const float* __restrict__ x, const float* __restrict__ vision,
            const int* __restrict__ mask, const float* __restrict__ Wu,
            const float* __restrict__ bu, const float* __restrict__ Wk,
            const float* __restrict__ Wv, float* __restrict__ out)
{
    extern __shared__ char dsm[];
    const int cta = blockIdx.x, tid = threadIdx.x;
    const int lane = tid & 31, wid = tid >> 5;

    // ============ P0: converts + maskT bitpack + bias fold ============
    if (cta < 116) {
        const int stride = 116 * 256;
        int base = cta * 256 + tid;
        for (int i = base; i < B_*V_*CV_/4; i += stride) {
            float4 v = ((const float4*)vision)[i];
            st_bf16x4((__nv_bfloat162*)g_visb, i, v);
        }
        for (int i = base; i < CV_*DIM_/4; i += stride) {
            float4 v = ((const float4*)Wu)[i];
            st_bf16x4((__nv_bfloat162*)g_Wub, i, v);
        }
        for (int i = base; i < DIM_*DIM_/4; i += stride) {
            float4 v = ((const float4*)Wk)[i];
            st_bf16x4((__nv_bfloat162*)g_Wkb, i, v);
        }
        for (int i = base; i < DIM_*DIM_/4; i += stride) {
            float4 v = ((const float4*)Wv)[i];
            st_bf16x4((__nv_bfloat162*)g_Wvb, i, v);
        }
        for (int i = base; i < B_*T_*DIM_/4; i += stride) {
            float4 v = ((const float4*)x)[i];
            st_bf16x4((__nv_bfloat162*)g_xb, i, v);
        }
        // maskT bitpack: tiles of 32 v x 256 t
        int* tile = (int*)dsm;   // [32][257]
        for (int job = cta; job < 128; job += 116) {
            int b = job >> 5, v0 = (job & 31) * 32;
            const int* mp = mask + (size_t)b * V_ * T_;
            __syncthreads();
            #pragma unroll
            for (int vr = 0; vr < 32; vr++)
                tile[vr * 257 + tid] = mp[(size_t)(v0 + vr) * T_ + tid];
            __syncthreads();
            unsigned word = 0;
            #pragma unroll
            for (int vr = 0; vr < 32; vr++)
                word |= (tile[vr * 257 + tid] != 0 ? 1u : 0u) << vr;
            g_maskT[((size_t)b * T_ + tid) * 32 + (job & 31)] = word;
        }
    } else {
        // bias fold: 32 CTAs, each 64 outputs, 4-way K split
        int idx = cta - 116;
        int kv = idx & 1, n0b = (idx >> 1) * 64;
        const float* W = kv ? Wv : Wk;
        int tx = tid & 63, ty = tid >> 6;
        float acc = 0.0f;
        int c0 = ty * 256;
        #pragma unroll 8
        for (int c = c0; c < c0 + 256; c++)
            acc = fmaf(bu[c], W[(size_t)c * DIM_ + n0b + tx], acc);
        float* sp = (float*)dsm;
        sp[ty * 64 + tx] = acc;
        __syncthreads();
        if (ty == 0)
            (kv ? g_buv : g_buk)[n0b + tx] = sp[tx] + sp[64+tx] + sp[128+tx] + sp[192+tx];
    }
    grid_sync();

    // ============ P1: Wuk/Wuv = Wu @ Wk/Wv, split-K=4 (128 jobs) ============
    if (cta < 128) {
        int kv = cta & 1, split = (cta >> 1) & 3, mt = (cta >> 3) & 1, nt = cta >> 4;
        int kbase = split * 256, m0 = mt * 128, n0 = nt * 128;
        const __nv_bfloat16* A = g_Wub + (size_t)m0 * DIM_ + kbase;
        const __nv_bfloat16* Bm = (kv ? g_Wvb : g_Wkb) + (size_t)kbase * DIM_ + n0;
        float d[2][8][4];
        tile_tn(A, DIM_, Bm, DIM_, 4, dsm, d);
        float* Cp = g_part[kv * 4 + split];
        FRAG_LOOP(
            *(float2*)(Cp + (size_t)(m0 + r0) * DIM_ + n0 + col)     = make_float2(d[fm][fn][0], d[fm][fn][1]);
            *(float2*)(Cp + (size_t)(m0 + r0 + 8) * DIM_ + n0 + col) = make_float2(d[fm][fn][2], d[fm][fn][3]); )
    }
    grid_sync();

    // ============ P2: reduce Wuk/Wuv -> bf16 ============
    for (int i = cta * 256 + tid; i < 131072; i += NCTA * 256) {
        int kv = i >> 16, j = i & 65535;
        float4 a = make_float4(0.f, 0.f, 0.f, 0.f);
        #pragma unroll
        for (int s = 0; s < 4; s++) {
            float4 p = ((const float4*)g_part[kv * 4 + s])[j];
            a.x += p.x; a.y += p.y; a.z += p.z; a.w += p.w;
        }
        st_bf16x4((__nv_bfloat162*)(kv ? g_Wuv : g_Wuk), j, a);
    }
    grid_sync();

    // ============ P3: xq = x @ Wuk^T, split-K=8 (128 jobs, fp32 partials) ============
    if (cta < 128) {
        int split = cta & 7, mt = (cta >> 3) & 7, nt = cta >> 6;
        int kbase = split * 128, m0 = mt * 128, n0 = nt * 128;
        const __nv_bfloat16* A = g_xb + (size_t)m0 * DIM_ + kbase;
        const __nv_bfloat16* Bm = g_Wuk + (size_t)n0 * DIM_ + kbase;
        float d[2][8][4];
        tile_nt(A, DIM_, Bm, DIM_, 2, dsm, d);
        float* Cp = g_part[split];
        FRAG_LOOP(
            *(float2*)(Cp + (size_t)(m0 + r0) * CV_ + n0 + col)     = make_float2(d[fm][fn][0], d[fm][fn][1]);
            *(float2*)(Cp + (size_t)(m0 + r0 + 8) * CV_ + n0 + col) = make_float2(d[fm][fn][2], d[fm][fn][3]); )
    }
    grid_sync();

    // ============ P4: FLASH — V-split x2, 128 CTAs ============
    // job: half = cta>>6; rem = cta&63; b = rem>>4; 16 tokens; 4 V-chunks.
    if (cta < 128) {
        const int half = cta >> 6, rem = cta & 63;
        const int b = rem >> 4, t0 = (rem & 15) * 16;
        char* Qs = dsm + F_OFF_Q;
        char* Ps = dsm + F_OFF_P;
        float* wred  = (float*)(dsm + F_OFF_WRED);   // [16][8]
        float* m_arr = (float*)(dsm + F_OFF_MSA);    // 16
        float* s_arr = m_arr + 16;
        float* f_arr = s_arr + 16;
        float* bd    = f_arr + 16;
        const int w8 = wid;
        const int r_lo = lane >> 2, r_hi = r_lo + 8;
        const int vrow0 = b * V_ + half * 512;       // gmem vision row base
        const int vbit0 = half * 512;                // mask bit base

        // vis chunk 0 prefetch
        #pragma unroll
        for (int h = 0; h < 16; h++) {
            int p = h * 256 + tid; int row = p >> 5, pc = p & 31;
            cp_async16(smem_u32(dsm + (row * 264 + pc * 8) * 2),
                       g_visb + ((size_t)(vrow0 + row)) * CV_ + pc * 8);
        }
        CP_COMMIT();

        // Q tile: reduce 16x256 from the 8 xq split partials -> bf16 smem
        #pragma unroll
        for (int h = 0; h < 16; h++) {
            int i = h * 256 + tid;
            int row = i >> 8, cc = i & 255;
            float acc = 0.0f;
            #pragma unroll
            for (int s = 0; s < 8; s++)
                acc += g_part[s][((size_t)(b * T_ + t0 + row) << 8) + cc];
            *(__nv_bfloat16*)(Qs + (row * 264 + cc) * 2) = __float2bfloat16(acc);
        }
        // bdot: warp w -> tokens 2w, 2w+1
        {
            int tk = wid * 2;
            #pragma unroll
            for (int u = 0; u < 2; u++) {
                const float* xr = x + ((size_t)(b * T_ + t0 + tk + u)) * DIM_;
                float acc = 0.0f;
                #pragma unroll
                for (int k = 0; k < 32; k++)
                    acc = fmaf(xr[k * 32 + lane], g_buk[k * 32 + lane], acc);
                #pragma unroll
                for (int off = 16; off > 0; off >>= 1)
                    acc += __shfl_down_sync(0xffffffffu, acc, off);
                if (lane == 0) bd[tk + u] = acc;
            }
        }
        if (tid < 16) { m_arr[tid] = -1e30f; s_arr[tid] = 0.0f; }

        float d2[4][4];
        #pragma unroll
        for (int i = 0; i < 4; i++)
            #pragma unroll
            for (int q = 0; q < 4; q++) d2[i][q] = 0.0f;

        for (int c = 0; c < 4; c++) {
            int buf = c & 1;
            if (c + 1 < 4) {
                int nbuf = (c + 1) & 1;
                #pragma unroll
                for (int h = 0; h < 16; h++) {
                    int p = h * 256 + tid; int row = p >> 5, pc = p & 31;
                    cp_async16(smem_u32(dsm + nbuf * F_VIS_STRIDE + (row * 264 + pc * 8) * 2),
                               g_visb + ((size_t)(vrow0 + (c + 1) * 128 + row)) * CV_ + pc * 8);
                }
                CP_COMMIT(); CP_WAIT(1);
            } else CP_WAIT(0);
            __syncthreads();
            char* VIS = dsm + buf * F_VIS_STRIDE;

            // --- mma1: logits tile [16 x 128] = Q[16,256] @ Vis[128,256]^T ---
            float d1[2][4];
            #pragma unroll
            for (int i = 0; i < 2; i++)
                #pragma unroll
                for (int q = 0; q < 4; q++) d1[i][q] = 0.0f;
            #pragma unroll
            for (int ks = 0; ks < 16; ks++) {
                uint32_t aF[4];
                int rA = lane & 15, kk = ks * 16 + (lane >> 4) * 8;
                ldmatrix_x4(aF, smem_u32(Qs + (rA * 264 + kk) * 2));
                int rb = w8 * 16 + (lane & 7) + (lane >> 4) * 8;
                int kkb = ks * 16 + ((lane >> 3) & 1) * 8;
                uint32_t t4[4];
                ldmatrix_x4(t4, smem_u32(VIS + (rb * 264 + kkb) * 2));
                uint32_t b0[2] = {t4[0], t4[1]}, b1[2] = {t4[2], t4[3]};
                mma16816(d1[0], aF, b0);
                mma16816(d1[1], aF, b1);
            }

            // --- masked online softmax stats ---
            int v0 = vbit0 + c * 128;
            unsigned wlo = g_maskT[((size_t)(b * T_ + t0 + r_lo)) * 32 + ((v0 + w8 * 16) >> 5)];
            unsigned whi = g_maskT[((size_t)(b * T_ + t0 + r_hi)) * 32 + ((v0 + w8 * 16) >> 5)];
            float lv[2][4]; bool mk[2][4];
            float mx0 = -1e30f, mx1 = -1e30f;
            #pragma unroll
            for (int fn = 0; fn < 2; fn++) {
                int cb = w8 * 16 + fn * 8 + 2 * (lane & 3);
                #pragma unroll
                for (int j = 0; j < 4; j++) {
                    int cc = cb + (j & 1);
                    bool hi = (j >> 1);
                    unsigned word = hi ? whi : wlo;
                    bool m = (word >> (cc & 31)) & 1u;
                    float l = (d1[fn][j] + bd[hi ? r_hi : r_lo]) * 0.03125f;
                    lv[fn][j] = l; mk[fn][j] = m;
                    if (m) { if (hi) mx1 = fmaxf(mx1, l); else mx0 = fmaxf(mx0, l); }
                }
            }
            #pragma unroll
            for (int off = 1; off <= 2; off <<= 1) {
                mx0 = fmaxf(mx0, __shfl_xor_sync(0xffffffffu, mx0, off));
                mx1 = fmaxf(mx1, __shfl_xor_sync(0xffffffffu, mx1, off));
            }
            if ((lane & 3) == 0) { wred[r_lo * 8 + w8] = mx0; wred[r_hi * 8 + w8] = mx1; }
            __syncthreads();
            if (tid < 16) {
                float tm = wred[tid * 8];
                #pragma unroll
                for (int k = 1; k < 8; k++) tm = fmaxf(tm, wred[tid * 8 + k]);
                float mo = m_arr[tid];
                float mn = fmaxf(mo, tm);
                f_arr[tid] = __expf(mo - mn);
                s_arr[tid] *= f_arr[tid];
                m_arr[tid] = mn;
            }
            __syncthreads();
            float mlo = m_arr[r_lo], mhi = m_arr[r_hi];
            float se0 = 0.0f, se1 = 0.0f;
            #pragma unroll
            for (int fn = 0; fn < 2; fn++) {
                int cb = w8 * 16 + fn * 8 + 2 * (lane & 3);
                float p0 = mk[fn][0] ? __expf(lv[fn][0] - mlo) : 0.0f;
                float p1 = mk[fn][1] ? __expf(lv[fn][1] - mlo) : 0.0f;
                float p2 = mk[fn][2] ? __expf(lv[fn][2] - mhi) : 0.0f;
                float p3 = mk[fn][3] ? __expf(lv[fn][3] - mhi) : 0.0f;
                se0 += p0 + p1; se1 += p2 + p3;
                *(__nv_bfloat162*)(Ps + (r_lo * 136 + cb) * 2) = __floats2bfloat162_rn(p0, p1);
                *(__nv_bfloat162*)(Ps + (r_hi * 136 + cb) * 2) = __floats2bfloat162_rn(p2, p3);
            }
            #pragma unroll
            for (int off = 1; off <= 2; off <<= 1) {
                se0 += __shfl_xor_sync(0xffffffffu, se0, off);
                se1 += __shfl_xor_sync(0xffffffffu, se1, off);
            }
            if ((lane & 3) == 0) { wred[r_lo * 8 + w8] = se0; wred[r_hi * 8 + w8] = se1; }
            float f0 = f_arr[r_lo], f1 = f_arr[r_hi];
            #pragma unroll
            for (int fn = 0; fn < 4; fn++) {
                d2[fn][0] *= f0; d2[fn][1] *= f0;
                d2[fn][2] *= f1; d2[fn][3] *= f1;
            }
            __syncthreads();
            if (tid < 16) {
                float ss = 0.0f;
                #pragma unroll
                for (int k = 0; k < 8; k++) ss += wred[tid * 8 + k];
                s_arr[tid] += ss;
            }

            // --- mma2: acc[16,256] += P[16,128] @ Vis[128,256] ---
            #pragma unroll
            for (int ks = 0; ks < 8; ks++) {
                uint32_t aF[4];
                int rA = lane & 15, kk = ks * 16 + (lane >> 4) * 8;
                ldmatrix_x4(aF, smem_u32(Ps + (rA * 136 + kk) * 2));
                #pragma unroll
                for (int i = 0; i < 2; i++) {
                    int kkb = ks * 16 + (lane & 15);
                    int nn = w8 * 32 + i * 16 + (lane >> 4) * 8;
                    uint32_t t4[4];
                    ldmatrix_x4_trans(t4, smem_u32(VIS + (kkb * 264 + nn) * 2));
                    uint32_t b0[2] = {t4[0], t4[1]}, b1[2] = {t4[2], t4[3]};
                    mma16816(d2[2*i], aF, b0);
                    mma16816(d2[2*i+1], aF, b1);
                }
            }
            __syncthreads();
        }
        // write fp32 partial agg + partial (m, s)
        float* AP = g_aggp[half];
        #pragma unroll
        for (int fn = 0; fn < 4; fn++) {
            int cb = w8 * 32 + fn * 8 + 2 * (lane & 3);
            *(float2*)(AP + ((size_t)(b * T_ + t0 + r_lo)) * CV_ + cb) =
                make_float2(d2[fn][0], d2[fn][1]);
            *(float2*)(AP + ((size_t)(b * T_ + t0 + r_hi)) * CV_ + cb) =
                make_float2(d2[fn][2], d2[fn][3]);
        }
        if (tid < 16) g_msp[half][b * T_ + t0 + tid] = make_float2(m_arr[tid], s_arr[tid]);
    }
    grid_sync();

    // ============ P5: MERGE V-halves -> g_agg (bf16) + g_ms ============
    for (int j = cta * 256 + tid; j < B_ * T_ * CV_ / 2; j += NCTA * 256) {
        int t = j >> 7;
        float2 p0 = g_msp[0][t], p1 = g_msp[1][t];
        float m = fmaxf(p0.x, p1.x);
        float f0 = __expf(p0.x - m), f1 = __expf(p1.x - m);
        float2 a0 = *(const float2*)(g_aggp[0] + 2 * (size_t)j);
        float2 a1 = *(const float2*)(g_aggp[1] + 2 * (size_t)j);
        ((__nv_bfloat162*)g_agg)[j] =
            __floats2bfloat162_rn(a0.x * f0 + a1.x * f1, a0.y * f0 + a1.y * f1);
        if ((j & 127) == 0)
            g_ms[t] = make_float2(m, p0.y * f0 + p1.y * f1);
    }
    grid_sync();

    // ============ P6: out = x + scale*(agg @ Wuv) + wsum*buv (64 jobs) ============
    if (cta < 64) {
        int mt = cta >> 3, nt = cta & 7;
        int m0 = mt * 128, n0 = nt * 128, b = m0 >> 8;
        // per-batch (M, S) reduce over 256 tokens
        float* rm = (float*)(dsm + 73728);
        float* rs = rm + 256;
        float2 v = g_ms[b * T_ + tid];
        rm[tid] = v.x; rs[tid] = v.y;
        __syncthreads();
        for (int st = 128; st > 0; st >>= 1) {
            if (tid < st) {
                float mm = rm[tid], ssv = rs[tid];
                ms_comb(mm, ssv, rm[tid + st], rs[tid + st]);
                rm[tid] = mm; rs[tid] = ssv;
            }
            __syncthreads();
        }
        float Mb = rm[0], Sb = rs[0];
        __syncthreads();

        float d[2][8][4];
        tile_tn(g_agg + (size_t)m0 * CV_, CV_, g_Wuv + n0, DIM_, 4, dsm, d);
        FRAG_LOOP(
            int r = m0 + r0;
            float2 ms0 = g_ms[r];
            float2 ms1 = g_ms[r + 8];
            float sc0 = __expf(ms0.x - Mb) / Sb;
            float sc1 = __expf(ms1.x - Mb) / Sb;
            float ws0 = ms0.y * sc0;
            float ws1 = ms1.y * sc1;
            float b0v = g_buv[n0 + col], b1v = g_buv[n0 + col + 1];
            float2 x0 = *(const float2*)(x + (size_t)r * DIM_ + n0 + col);
            float2 x1 = *(const float2*)(x + (size_t)(r + 8) * DIM_ + n0 + col);
            *(float2*)(out + (size_t)r * DIM_ + n0 + col) =
                make_float2(sc0 * d[fm][fn][0] + x0.x + ws0 * b0v,
                            sc0 * d[fm][fn][1] + x0.y + ws0 * b1v);
            *(float2*)(out + (size_t)(r + 8) * DIM_ + n0 + col) =
                make_float2(sc1 * d[fm][fn][2] + x1.x + ws1 * b0v,
                            sc1 * d[fm][fn][3] + x1.y + ws1 * b1v); )
    }
}

// ---------------------------------------------------------------------------
// Launch: ONE kernel
// ---------------------------------------------------------------------------
extern "C" void kernel_launch(void* const* d_in, const int* in_sizes, int n_in,
                              void* d_out, int out_size)
{
    const float* x      = (const float*)d_in[0];
    const float* vision = (const float*)d_in[1];
    const int*   mask   = (const int*)  d_in[2];
    const float* Wu     = (const float*)d_in[3];
    const float* bu     = (const float*)d_in[4];
    const float* Wk     = (const float*)d_in[5];
    const float* Wv     = (const float*)d_in[6];

    static int init_done = 0;
    if (!init_done) {
        cudaFuncSetAttribute(mega_kernel,
                             cudaFuncAttributeMaxDynamicSharedMemorySize, DSM_BYTES);
        init_done = 1;
    }

    mega_kernel<<<NCTA, 256, DSM_BYTES>>>(x, vision, mask, Wu, bu, Wk, Wv, (float*)d_out);
}

// round 13
// speedup vs baseline: 1.6602x; 1.0303x over previous
#include <cuda_runtime.h>
#include <cuda_bf16.h>
#include <cstdint>
#include <math.h>

#define B_   4
#define T_   256
#define V_   1024
#define DIM_ 1024
#define CV_  256
#define NCTA 148

// ---------------------------------------------------------------------------
// Scratch (static device globals)
// ---------------------------------------------------------------------------
__device__ __nv_bfloat16 g_visb[B_ * V_ * CV_];   // vision bf16
__device__ __nv_bfloat16 g_Wuk [CV_ * DIM_];      // Wu@Wk bf16
__device__ __nv_bfloat16 g_Wuv [CV_ * DIM_];      // Wu@Wv bf16
__device__ float         g_part[8][CV_ * DIM_];   // split-K partials
__device__ float         g_buk [DIM_];
__device__ float         g_buv [DIM_];
__device__ unsigned      g_maskT [B_ * T_ * (V_ / 32)]; // bit-packed (b,t,v)
__device__ float         g_aggp[2][B_ * T_ * CV_];// flash V-half partial agg (fp32)
__device__ float2        g_msp [2][B_ * T_];      // flash V-half partial (m,s)
__device__ unsigned      g_bar_cnt;
__device__ unsigned      g_bar_gen;

// ---------------------------------------------------------------------------
// helpers
// ---------------------------------------------------------------------------
__device__ __forceinline__ uint32_t smem_u32(const void* p) {
    uint32_t a;
    asm("{ .reg .u64 t; cvta.to.shared.u64 t, %1; cvt.u32.u64 %0, t; }"
        : "=r"(a) : "l"(p));
    return a;
}
__device__ __forceinline__ void cp_async16(uint32_t dst, const void* src) {
    asm volatile("cp.async.cg.shared.global [%0], [%1], 16;" :: "r"(dst), "l"(src));
}
#define CP_COMMIT() asm volatile("cp.async.commit_group;" ::: "memory")
#define CP_WAIT(n)  asm volatile("cp.async.wait_group %0;" :: "n"(n) : "memory")

__device__ __forceinline__ void ldmatrix_x4(uint32_t* r, uint32_t addr) {
    asm volatile("ldmatrix.sync.aligned.m8n8.x4.shared.b16 {%0,%1,%2,%3}, [%4];"
                 : "=r"(r[0]), "=r"(r[1]), "=r"(r[2]), "=r"(r[3]) : "r"(addr));
}
__device__ __forceinline__ void ldmatrix_x4_trans(uint32_t* r, uint32_t addr) {
    asm volatile("ldmatrix.sync.aligned.m8n8.x4.trans.shared.b16 {%0,%1,%2,%3}, [%4];"
                 : "=r"(r[0]), "=r"(r[1]), "=r"(r[2]), "=r"(r[3]) : "r"(addr));
}
__device__ __forceinline__ void mma16816(float* d, const uint32_t* a, const uint32_t* b) {
    asm volatile(
        "mma.sync.aligned.m16n8k16.row.col.f32.bf16.bf16.f32 "
        "{%0,%1,%2,%3},{%4,%5,%6,%7},{%8,%9},{%0,%1,%2,%3};"
        : "+f"(d[0]), "+f"(d[1]), "+f"(d[2]), "+f"(d[3])
        : "r"(a[0]), "r"(a[1]), "r"(a[2]), "r"(a[3]), "r"(b[0]), "r"(b[1]));
}

// grid-wide barrier (all NCTA CTAs co-resident: 1 CTA/SM)
__device__ __forceinline__ void grid_sync() {
    __syncthreads();
    if (threadIdx.x == 0) {
        volatile unsigned* vgen = &g_bar_gen;
        unsigned gen = *vgen;
        __threadfence();
        if (atomicAdd(&g_bar_cnt, 1u) == NCTA - 1) {
            g_bar_cnt = 0u;
            __threadfence();
            *(volatile unsigned*)&g_bar_gen = gen + 1u;
        } else {
            while (*vgen == gen) { }
        }
        __threadfence();
    }
    __syncthreads();
}

__device__ __forceinline__ void ms_comb(float& m, float& s, float m2, float s2) {
    float nm = fmaxf(m, m2);
    s = s * __expf(m - nm) + s2 * __expf(m2 - nm);
    m = nm;
}
__device__ __forceinline__ void st_bf16x4(__nv_bfloat162* o, int i, float4 a) {
    o[2 * i]     = __floats2bfloat162_rn(a.x, a.y);
    o[2 * i + 1] = __floats2bfloat162_rn(a.z, a.w);
}
__device__ __forceinline__ void st_bf16x4_smem(void* p, float4 v) {
    __nv_bfloat162 h0 = __floats2bfloat162_rn(v.x, v.y);
    __nv_bfloat162 h1 = __floats2bfloat162_rn(v.z, v.w);
    uint2 u;
    u.x = *(uint32_t*)&h0;
    u.y = *(uint32_t*)&h1;
    *(uint2*)p = u;
}

// Flash smem layout
#define F_VIS_STRIDE 67584            // 128*264*2
#define F_OFF_Q      135168
#define F_OFF_P      143616
#define F_OFF_WRED   147968
#define F_OFF_MSA    148480
#define DSM_BYTES    148736

// P6 smem layout
#define P6_BS_OFF    67584
#define P6_ARR_OFF   102912

// ---------------------------------------------------------------------------
// tile_p1: C += A_f32[128,K] @ B_f32[K,128]  (convert-on-load, reg-staged)
// ---------------------------------------------------------------------------
__device__ __forceinline__ void tile_p1(const float* __restrict__ A, int lda,
                                        const float* __restrict__ Bm, int ldb,
                                        int nchunks, char* dsm, float d[2][8][4]) {
    const int tid = threadIdx.x, lane = tid & 31, wid = tid >> 5;
    const int warpM = wid & 3, warpN = wid >> 2;
    __nv_bfloat16* As = (__nv_bfloat16*)dsm;             // [128][72]
    __nv_bfloat16* Bs = (__nv_bfloat16*)(dsm + 18432);   // [64][136]
    #pragma unroll
    for (int i = 0; i < 2; i++)
        #pragma unroll
        for (int j = 0; j < 8; j++)
            #pragma unroll
            for (int q = 0; q < 4; q++) d[i][j][q] = 0.0f;

    float4 ar[8], br[8];
    auto ldA = [&](int c) {
        #pragma unroll
        for (int h = 0; h < 8; h++) {
            int i = h * 256 + tid, row = i >> 4, pc = i & 15;
            ar[h] = *(const float4*)(A + (size_t)row * lda + c * 64 + pc * 4);
        }
    };
    auto ldB = [&](int c) {
        #pragma unroll
        for (int h = 0; h < 8; h++) {
            int i = h * 256 + tid, row = i >> 5, pc = i & 31;
            br[h] = *(const float4*)(Bm + (size_t)(c * 64 + row) * ldb + pc * 4);
        }
    };
    ldA(0); ldB(0);
    for (int c = 0; c < nchunks; c++) {
        __syncthreads();
        #pragma unroll
        for (int h = 0; h < 8; h++) {
            int i = h * 256 + tid, row = i >> 4, pc = i & 15;
            st_bf16x4_smem(As + row * 72 + pc * 4, ar[h]);
        }
        #pragma unroll
        for (int h = 0; h < 8; h++) {
            int i = h * 256 + tid, row = i >> 5, pc = i & 31;
            st_bf16x4_smem(Bs + row * 136 + pc * 4, br[h]);
        }
        if (c + 1 < nchunks) { ldA(c + 1); ldB(c + 1); }
        __syncthreads();
        #pragma unroll
        for (int ks = 0; ks < 4; ks++) {
            uint32_t a[2][4];
            #pragma unroll
            for (int fm = 0; fm < 2; fm++) {
                int r  = warpM * 32 + fm * 16 + (lane & 7) + ((lane >> 3) & 1) * 8;
                int kk = ks * 16 + (lane >> 4) * 8;
                ldmatrix_x4(a[fm], smem_u32(As + r * 72 + kk));
            }
            uint32_t b[8][2];
            #pragma unroll
            for (int i = 0; i < 4; i++) {
                int kk = ks * 16 + (lane & 15);
                int nn = warpN * 64 + i * 16 + (lane >> 4) * 8;
                uint32_t tmp[4];
                ldmatrix_x4_trans(tmp, smem_u32(Bs + kk * 136 + nn));
                b[2*i][0]   = tmp[0]; b[2*i][1]   = tmp[1];
                b[2*i+1][0] = tmp[2]; b[2*i+1][1] = tmp[3];
            }
            #pragma unroll
            for (int fm = 0; fm < 2; fm++)
                #pragma unroll
                for (int fn = 0; fn < 8; fn++)
                    mma16816(d[fm][fn], a[fm], b[fn]);
        }
    }
    __syncthreads();
}

// ---------------------------------------------------------------------------
// tile_p3: C += A_f32[128,K] @ B_bf16[128,K]^T (A convert-on-load, B reg-staged)
// ---------------------------------------------------------------------------
__device__ __forceinline__ void tile_p3(const float* __restrict__ A, int lda,
                                        const __nv_bfloat16* __restrict__ Bm, int ldb,
                                        int nchunks, char* dsm, float d[2][8][4]) {
    const int tid = threadIdx.x, lane = tid & 31, wid = tid >> 5;
    const int warpM = wid & 3, warpN = wid >> 2;
    __nv_bfloat16* As = (__nv_bfloat16*)dsm;             // [128][72]
    __nv_bfloat16* Bs = (__nv_bfloat16*)(dsm + 18432);   // [128][72]
    #pragma unroll
    for (int i = 0; i < 2; i++)
        #pragma unroll
        for (int j = 0; j < 8; j++)
            #pragma unroll
            for (int q = 0; q < 4; q++) d[i][j][q] = 0.0f;

    float4 ar[8];
    uint4 br4[4];
    auto ldA = [&](int c) {
        #pragma unroll
        for (int h = 0; h < 8; h++) {
            int i = h * 256 + tid, row = i >> 4, pc = i & 15;
            ar[h] = *(const float4*)(A + (size_t)row * lda + c * 64 + pc * 4);
        }
    };
    auto ldB = [&](int c) {
        #pragma unroll
        for (int h = 0; h < 4; h++) {
            int i = h * 256 + tid, row = i >> 3, pc = i & 7;
            br4[h] = *(const uint4*)(Bm + (size_t)row * ldb + c * 64 + pc * 8);
        }
    };
    ldA(0); ldB(0);
    for (int c = 0; c < nchunks; c++) {
        __syncthreads();
        #pragma unroll
        for (int h = 0; h < 8; h++) {
            int i = h * 256 + tid, row = i >> 4, pc = i & 15;
            st_bf16x4_smem(As + row * 72 + pc * 4, ar[h]);
        }
        #pragma unroll
        for (int h = 0; h < 4; h++) {
            int i = h * 256 + tid, row = i >> 3, pc = i & 7;
            *(uint4*)(Bs + row * 72 + pc * 8) = br4[h];
        }
        if (c + 1 < nchunks) { ldA(c + 1); ldB(c + 1); }
        __syncthreads();
        #pragma unroll
        for (int ks = 0; ks < 4; ks++) {
            uint32_t a[2][4];
            #pragma unroll
            for (int fm = 0; fm < 2; fm++) {
                int r  = warpM * 32 + fm * 16 + (lane & 7) + ((lane >> 3) & 1) * 8;
                int kk = ks * 16 + (lane >> 4) * 8;
                ldmatrix_x4(a[fm], smem_u32(As + r * 72 + kk));
            }
            uint32_t b[8][2];
            #pragma unroll
            for (int i = 0; i < 4; i++) {
                int r  = warpN * 64 + i * 16 + (lane & 7) + (lane >> 4) * 8;
                int kk = ks * 16 + ((lane >> 3) & 1) * 8;
                uint32_t tmp[4];
                ldmatrix_x4(tmp, smem_u32(Bs + r * 72 + kk));
                b[2*i][0]   = tmp[0]; b[2*i][1]   = tmp[1];
                b[2*i+1][0] = tmp[2]; b[2*i+1][1] = tmp[3];
            }
            #pragma unroll
            for (int fm = 0; fm < 2; fm++)
                #pragma unroll
                for (int fn = 0; fn < 8; fn++)
                    mma16816(d[fm][fn], a[fm], b[fn]);
        }
    }
    __syncthreads();
}

#define FRAG_LOOP(...) \
    { const int lane_ = threadIdx.x & 31, wid_ = threadIdx.x >> 5; \
      const int warpM_ = wid_ & 3, warpN_ = wid_ >> 2; \
      _Pragma("unroll") for (int fm = 0; fm < 2; fm++) \
      _Pragma("unroll") for (int fn = 0; fn < 8; fn++) { \
          int r0  = warpM_ * 32 + fm * 16 + (lane_ >> 2); \
          int col = warpN_ * 64 + fn * 8 + 2 * (lane_ & 3); \
          __VA_ARGS__ } }

// ---------------------------------------------------------------------------
// The persistent mega-kernel
// ---------------------------------------------------------------------------
extern "C" __global__ void __launch_bounds__(256)
mega_kernel(const float* __restrict__ x, const float* __restrict__ vision,
            const int* __restrict__ mask, const float* __restrict__ Wu,
            const float* __restrict__ bu, const float* __restrict__ Wk,
            const float* __restrict__ Wv, float* __restrict__ out)
{
    extern __shared__ char dsm[];
    const int cta = blockIdx.x, tid = threadIdx.x;
    const int lane = tid & 31, wid = tid >> 5;

    // ============ P0: vision convert + maskT bitpack + bias fold ============
    if (cta < 116) {
        const int stride = 116 * 256;
        for (int i = cta * 256 + tid; i < B_*V_*CV_/4; i += stride) {
            float4 v = ((const float4*)vision)[i];
            st_bf16x4((__nv_bfloat162*)g_visb, i, v);
        }
        // maskT bitpack: tiles of 32 v x 256 t
        int* tile = (int*)dsm;   // [32][257]
        for (int job = cta; job < 128; job += 116) {
            int b = job >> 5, v0 = (job & 31) * 32;
            const int* mp = mask + (size_t)b * V_ * T_;
            __syncthreads();
            #pragma unroll
            for (int vr = 0; vr < 32; vr++)
                tile[vr * 257 + tid] = mp[(size_t)(v0 + vr) * T_ + tid];
            __syncthreads();
            unsigned word = 0;
            #pragma unroll
            for (int vr = 0; vr < 32; vr++)
                word |= (tile[vr * 257 + tid] != 0 ? 1u : 0u) << vr;
            g_maskT[((size_t)b * T_ + tid) * 32 + (job & 31)] = word;
        }
    } else {
        // bias fold: 32 CTAs, each 64 outputs, 4-way K split
        int idx = cta - 116;
        int kv = idx & 1, n0b = (idx >> 1) * 64;
        const float* W = kv ? Wv : Wk;
        int tx = tid & 63, ty = tid >> 6;
        float acc = 0.0f;
        int c0 = ty * 256;
        #pragma unroll 8
        for (int c = c0; c < c0 + 256; c++)
            acc = fmaf(bu[c], W[(size_t)c * DIM_ + n0b + tx], acc);
        float* sp = (float*)dsm;
        sp[ty * 64 + tx] = acc;
        __syncthreads();
        if (ty == 0)
            (kv ? g_buv : g_buk)[n0b + tx] = sp[tx] + sp[64+tx] + sp[128+tx] + sp[192+tx];
    }
    grid_sync();

    // ============ P1: Wuk/Wuv = Wu @ Wk/Wv, split-K=4, fp32 in (128 jobs) ============
    if (cta < 128) {
        int kv = cta & 1, split = (cta >> 1) & 3, mt = (cta >> 3) & 1, nt = cta >> 4;
        int kbase = split * 256, m0 = mt * 128, n0 = nt * 128;
        const float* A = Wu + (size_t)m0 * DIM_ + kbase;
        const float* Bm = (kv ? Wv : Wk) + (size_t)kbase * DIM_ + n0;
        float d[2][8][4];
        tile_p1(A, DIM_, Bm, DIM_, 4, dsm, d);
        float* Cp = g_part[kv * 4 + split];
        FRAG_LOOP(
            *(float2*)(Cp + (size_t)(m0 + r0) * DIM_ + n0 + col)     = make_float2(d[fm][fn][0], d[fm][fn][1]);
            *(float2*)(Cp + (size_t)(m0 + r0 + 8) * DIM_ + n0 + col) = make_float2(d[fm][fn][2], d[fm][fn][3]); )
    }
    grid_sync();

    // ============ P2: reduce Wuk/Wuv -> bf16 ============
    for (int i = cta * 256 + tid; i < 131072; i += NCTA * 256) {
        int kv = i >> 16, j = i & 65535;
        float4 a = make_float4(0.f, 0.f, 0.f, 0.f);
        #pragma unroll
        for (int s = 0; s < 4; s++) {
            float4 p = ((const float4*)g_part[kv * 4 + s])[j];
            a.x += p.x; a.y += p.y; a.z += p.z; a.w += p.w;
        }
        st_bf16x4((__nv_bfloat162*)(kv ? g_Wuv : g_Wuk), j, a);
    }
    grid_sync();

    // ============ P3: xq = x @ Wuk^T, split-K=8, fp32 A (128 jobs) ============
    if (cta < 128) {
        int split = cta & 7, mt = (cta >> 3) & 7, nt = cta >> 6;
        int kbase = split * 128, m0 = mt * 128, n0 = nt * 128;
        const float* A = x + (size_t)m0 * DIM_ + kbase;
        const __nv_bfloat16* Bm = g_Wuk + (size_t)n0 * DIM_ + kbase;
        float d[2][8][4];
        tile_p3(A, DIM_, Bm, DIM_, 2, dsm, d);
        float* Cp = g_part[split];
        FRAG_LOOP(
            *(float2*)(Cp + (size_t)(m0 + r0) * CV_ + n0 + col)     = make_float2(d[fm][fn][0], d[fm][fn][1]);
            *(float2*)(Cp + (size_t)(m0 + r0 + 8) * CV_ + n0 + col) = make_float2(d[fm][fn][2], d[fm][fn][3]); )
    }
    grid_sync();

    // ============ P4: FLASH — V-split x2, 128 CTAs ============
    if (cta < 128) {
        const int half = cta >> 6, rem = cta & 63;
        const int b = rem >> 4, t0 = (rem & 15) * 16;
        char* Qs = dsm + F_OFF_Q;
        char* Ps = dsm + F_OFF_P;
        float* wred  = (float*)(dsm + F_OFF_WRED);   // [16][8]
        float* m_arr = (float*)(dsm + F_OFF_MSA);    // 16
        float* s_arr = m_arr + 16;
        float* f_arr = s_arr + 16;
        float* bd    = f_arr + 16;
        const int w8 = wid;
        const int r_lo = lane >> 2, r_hi = r_lo + 8;
        const int vrow0 = b * V_ + half * 512;
        const int vbit0 = half * 512;

        #pragma unroll
        for (int h = 0; h < 16; h++) {
            int p = h * 256 + tid; int row = p >> 5, pc = p & 31;
            cp_async16(smem_u32(dsm + (row * 264 + pc * 8) * 2),
                       g_visb + ((size_t)(vrow0 + row)) * CV_ + pc * 8);
        }
        CP_COMMIT();

        // Q tile: reduce 16x256 from the 8 xq split partials -> bf16 smem
        #pragma unroll
        for (int h = 0; h < 16; h++) {
            int i = h * 256 + tid;
            int row = i >> 8, cc = i & 255;
            float acc = 0.0f;
            #pragma unroll
            for (int s = 0; s < 8; s++)
                acc += g_part[s][((size_t)(b * T_ + t0 + row) << 8) + cc];
            *(__nv_bfloat16*)(Qs + (row * 264 + cc) * 2) = __float2bfloat16(acc);
        }
        // bdot: warp w -> tokens 2w, 2w+1
        {
            int tk = wid * 2;
            #pragma unroll
            for (int u = 0; u < 2; u++) {
                const float* xr = x + ((size_t)(b * T_ + t0 + tk + u)) * DIM_;
                float acc = 0.0f;
                #pragma unroll
                for (int k = 0; k < 32; k++)
                    acc = fmaf(xr[k * 32 + lane], g_buk[k * 32 + lane], acc);
                #pragma unroll
                for (int off = 16; off > 0; off >>= 1)
                    acc += __shfl_down_sync(0xffffffffu, acc, off);
                if (lane == 0) bd[tk + u] = acc;
            }
        }
        if (tid < 16) { m_arr[tid] = -1e30f; s_arr[tid] = 0.0f; }

        float d2[4][4];
        #pragma unroll
        for (int i = 0; i < 4; i++)
            #pragma unroll
            for (int q = 0; q < 4; q++) d2[i][q] = 0.0f;

        for (int c = 0; c < 4; c++) {
            int buf = c & 1;
            if (c + 1 < 4) {
                int nbuf = (c + 1) & 1;
                #pragma unroll
                for (int h = 0; h < 16; h++) {
                    int p = h * 256 + tid; int row = p >> 5, pc = p & 31;
                    cp_async16(smem_u32(dsm + nbuf * F_VIS_STRIDE + (row * 264 + pc * 8) * 2),
                               g_visb + ((size_t)(vrow0 + (c + 1) * 128 + row)) * CV_ + pc * 8);
                }
                CP_COMMIT(); CP_WAIT(1);
            } else CP_WAIT(0);
            __syncthreads();
            char* VIS = dsm + buf * F_VIS_STRIDE;

            // --- mma1: logits tile [16 x 128] ---
            float d1[2][4];
            #pragma unroll
            for (int i = 0; i < 2; i++)
                #pragma unroll
                for (int q = 0; q < 4; q++) d1[i][q] = 0.0f;
            #pragma unroll
            for (int ks = 0; ks < 16; ks++) {
                uint32_t aF[4];
                int rA = lane & 15, kk = ks * 16 + (lane >> 4) * 8;
                ldmatrix_x4(aF, smem_u32(Qs + (rA * 264 + kk) * 2));
                int rb = w8 * 16 + (lane & 7) + (lane >> 4) * 8;
                int kkb = ks * 16 + ((lane >> 3) & 1) * 8;
                uint32_t t4[4];
                ldmatrix_x4(t4, smem_u32(VIS + (rb * 264 + kkb) * 2));
                uint32_t b0[2] = {t4[0], t4[1]}, b1[2] = {t4[2], t4[3]};
                mma16816(d1[0], aF, b0);
                mma16816(d1[1], aF, b1);
            }

            // --- masked online softmax ---
            int v0 = vbit0 + c * 128;
            unsigned wlo = g_maskT[((size_t)(b * T_ + t0 + r_lo)) * 32 + ((v0 + w8 * 16) >> 5)];
            unsigned whi = g_maskT[((size_t)(b * T_ + t0 + r_hi)) * 32 + ((v0 + w8 * 16) >> 5)];
            float lv[2][4]; bool mk[2][4];
            float mx0 = -1e30f, mx1 = -1e30f;
            #pragma unroll
            for (int fn = 0; fn < 2; fn++) {
                int cb = w8 * 16 + fn * 8 + 2 * (lane & 3);
                #pragma unroll
                for (int j = 0; j < 4; j++) {
                    int cc = cb + (j & 1);
                    bool hi = (j >> 1);
                    unsigned word = hi ? whi : wlo;
                    bool m = (word >> (cc & 31)) & 1u;
                    float l = (d1[fn][j] + bd[hi ? r_hi : r_lo]) * 0.03125f;
                    lv[fn][j] = l; mk[fn][j] = m;
                    if (m) { if (hi) mx1 = fmaxf(mx1, l); else mx0 = fmaxf(mx0, l); }
                }
            }
            #pragma unroll
            for (int off = 1; off <= 2; off <<= 1) {
                mx0 = fmaxf(mx0, __shfl_xor_sync(0xffffffffu, mx0, off));
                mx1 = fmaxf(mx1, __shfl_xor_sync(0xffffffffu, mx1, off));
            }
            if ((lane & 3) == 0) { wred[r_lo * 8 + w8] = mx0; wred[r_hi * 8 + w8] = mx1; }
            __syncthreads();
            if (tid < 16) {
                float tmv = wred[tid * 8];
                #pragma unroll
                for (int k = 1; k < 8; k++) tmv = fmaxf(tmv, wred[tid * 8 + k]);
                float mo = m_arr[tid];
                float mn = fmaxf(mo, tmv);
                f_arr[tid] = __expf(mo - mn);
                s_arr[tid] *= f_arr[tid];
                m_arr[tid] = mn;
            }
            __syncthreads();
            float mlo = m_arr[r_lo], mhi = m_arr[r_hi];
            float se0 = 0.0f, se1 = 0.0f;
            #pragma unroll
            for (int fn = 0; fn < 2; fn++) {
                int cb = w8 * 16 + fn * 8 + 2 * (lane & 3);
                float p0 = mk[fn][0] ? __expf(lv[fn][0] - mlo) : 0.0f;
                float p1 = mk[fn][1] ? __expf(lv[fn][1] - mlo) : 0.0f;
                float p2 = mk[fn][2] ? __expf(lv[fn][2] - mhi) : 0.0f;
                float p3 = mk[fn][3] ? __expf(lv[fn][3] - mhi) : 0.0f;
                se0 += p0 + p1; se1 += p2 + p3;
                *(__nv_bfloat162*)(Ps + (r_lo * 136 + cb) * 2) = __floats2bfloat162_rn(p0, p1);
                *(__nv_bfloat162*)(Ps + (r_hi * 136 + cb) * 2) = __floats2bfloat162_rn(p2, p3);
            }
            #pragma unroll
            for (int off = 1; off <= 2; off <<= 1) {
                se0 += __shfl_xor_sync(0xffffffffu, se0, off);
                se1 += __shfl_xor_sync(0xffffffffu, se1, off);
            }
            if ((lane & 3) == 0) { wred[r_lo * 8 + w8] = se0; wred[r_hi * 8 + w8] = se1; }
            float f0 = f_arr[r_lo], f1 = f_arr[r_hi];
            #pragma unroll
            for (int fn = 0; fn < 4; fn++) {
                d2[fn][0] *= f0; d2[fn][1] *= f0;
                d2[fn][2] *= f1; d2[fn][3] *= f1;
            }
            __syncthreads();
            if (tid < 16) {
                float ss = 0.0f;
                #pragma unroll
                for (int k = 0; k < 8; k++) ss += wred[tid * 8 + k];
                s_arr[tid] += ss;
            }

            // --- mma2: acc += P @ Vis ---
            #pragma unroll
            for (int ks = 0; ks < 8; ks++) {
                uint32_t aF[4];
                int rA = lane & 15, kk = ks * 16 + (lane >> 4) * 8;
                ldmatrix_x4(aF, smem_u32(Ps + (rA * 136 + kk) * 2));
                #pragma unroll
                for (int i = 0; i < 2; i++) {
                    int kkb = ks * 16 + (lane & 15);
                    int nn = w8 * 32 + i * 16 + (lane >> 4) * 8;
                    uint32_t t4[4];
                    ldmatrix_x4_trans(t4, smem_u32(VIS + (kkb * 264 + nn) * 2));
                    uint32_t b0[2] = {t4[0], t4[1]}, b1[2] = {t4[2], t4[3]};
                    mma16816(d2[2*i], aF, b0);
                    mma16816(d2[2*i+1], aF, b1);
                }
            }
            __syncthreads();
        }
        float* AP = g_aggp[half];
        #pragma unroll
        for (int fn = 0; fn < 4; fn++) {
            int cb = w8 * 32 + fn * 8 + 2 * (lane & 3);
            *(float2*)(AP + ((size_t)(b * T_ + t0 + r_lo)) * CV_ + cb) =
                make_float2(d2[fn][0], d2[fn][1]);
            *(float2*)(AP + ((size_t)(b * T_ + t0 + r_hi)) * CV_ + cb) =
                make_float2(d2[fn][2], d2[fn][3]);
        }
        if (tid < 16) g_msp[half][b * T_ + t0 + tid] = make_float2(m_arr[tid], s_arr[tid]);
    }
    grid_sync();

    // ============ P5: out = x + scale*((merged agg) @ Wuv) + wsum*buv (64 jobs) ============
    if (cta < 64) {
        const int mt = cta >> 3, nt = cta & 7;
        const int m0 = mt * 128, n0 = nt * 128, b = mt >> 1;
        const int tb0 = (mt & 1) * 128;
        const int warpM = wid & 3, warpN = wid >> 2;

        __nv_bfloat16* As = (__nv_bfloat16*)dsm;         // [128][264]
        char* BsBase = dsm + P6_BS_OFF;                  // 2 x [64][136]
        float* tm  = (float*)(dsm + P6_ARR_OFF);
        float* ts  = tm + 256;
        float* fa0 = ts + 256;
        float* fa1 = fa0 + 256;
        float* rm  = fa1 + 256;
        float* rs  = rm + 256;

        // prefetch B chunk 0 (Wuv rows 0..63)
        #pragma unroll
        for (int h = 0; h < 4; h++) {
            int i = h * 256 + tid, row = i >> 4, pc = i & 15;
            cp_async16(smem_u32(BsBase + (row * 136 + pc * 8) * 2),
                       g_Wuv + (size_t)row * DIM_ + n0 + pc * 8);
        }
        CP_COMMIT();

        // merged per-token stats for batch b
        {
            float2 p0 = g_msp[0][b * T_ + tid], p1 = g_msp[1][b * T_ + tid];
            float mmv = fmaxf(p0.x, p1.x);
            float f0 = __expf(p0.x - mmv), f1 = __expf(p1.x - mmv);
            tm[tid] = mmv; ts[tid] = p0.y * f0 + p1.y * f1;
            fa0[tid] = f0; fa1[tid] = f1;
        }
        __syncthreads();
        rm[tid] = tm[tid]; rs[tid] = ts[tid];
        __syncthreads();
        for (int st = 128; st > 0; st >>= 1) {
            if (tid < st) {
                float mmv = rm[tid], ssv = rs[tid];
                ms_comb(mmv, ssv, rm[tid + st], rs[tid + st]);
                rm[tid] = mmv; rs[tid] = ssv;
            }
            __syncthreads();
        }
        const float Mb = rm[0], Sb = rs[0];

        // A merge: 128x256 fp32 halves -> bf16 smem
        for (int i = tid; i < 128 * 64; i += 256) {
            int row = i >> 6, pc = i & 63;
            float4 a0 = *(const float4*)(g_aggp[0] + ((size_t)(m0 + row)) * CV_ + pc * 4);
            float4 a1 = *(const float4*)(g_aggp[1] + ((size_t)(m0 + row)) * CV_ + pc * 4);
            float f0 = fa0[tb0 + row], f1 = fa1[tb0 + row];
            float4 mg = make_float4(a0.x * f0 + a1.x * f1, a0.y * f0 + a1.y * f1,
                                    a0.z * f0 + a1.z * f1, a0.w * f0 + a1.w * f1);
            st_bf16x4_smem(As + row * 264 + pc * 4, mg);
        }
        __syncthreads();

        float d[2][8][4];
        #pragma unroll
        for (int i = 0; i < 2; i++)
            #pragma unroll
            for (int j = 0; j < 8; j++)
                #pragma unroll
                for (int q = 0; q < 4; q++) d[i][j][q] = 0.0f;

        for (int c = 0; c < 4; c++) {
            int buf = c & 1;
            if (c + 1 < 4) {
                int nbuf = (c + 1) & 1;
                #pragma unroll
                for (int h = 0; h < 4; h++) {
                    int i = h * 256 + tid, row = i >> 4, pc = i & 15;
                    cp_async16(smem_u32(BsBase + nbuf * 17408 + (row * 136 + pc * 8) * 2),
                               g_Wuv + (size_t)((c + 1) * 64 + row) * DIM_ + n0 + pc * 8);
                }
                CP_COMMIT(); CP_WAIT(1);
            } else CP_WAIT(0);
            __syncthreads();
            __nv_bfloat16* Bs = (__nv_bfloat16*)(BsBase + buf * 17408);
            #pragma unroll
            for (int ks = 0; ks < 4; ks++) {
                uint32_t a[2][4];
                #pragma unroll
                for (int fm = 0; fm < 2; fm++) {
                    int r  = warpM * 32 + fm * 16 + (lane & 7) + ((lane >> 3) & 1) * 8;
                    int kk = c * 64 + ks * 16 + (lane >> 4) * 8;
                    ldmatrix_x4(a[fm], smem_u32(As + r * 264 + kk));
                }
                uint32_t bfr[8][2];
                #pragma unroll
                for (int i = 0; i < 4; i++) {
                    int kk = ks * 16 + (lane & 15);
                    int nn = warpN * 64 + i * 16 + (lane >> 4) * 8;
                    uint32_t tmp[4];
                    ldmatrix_x4_trans(tmp, smem_u32(Bs + kk * 136 + nn));
                    bfr[2*i][0]   = tmp[0]; bfr[2*i][1]   = tmp[1];
                    bfr[2*i+1][0] = tmp[2]; bfr[2*i+1][1] = tmp[3];
                }
                #pragma unroll
                for (int fm = 0; fm < 2; fm++)
                    #pragma unroll
                    for (int fn = 0; fn < 8; fn++)
                        mma16816(d[fm][fn], a[fm], bfr[fn]);
            }
            __syncthreads();
        }

        FRAG_LOOP(
            int r = m0 + r0;
            float sc0 = __expf(tm[tb0 + r0] - Mb) / Sb;
            float sc1 = __expf(tm[tb0 + r0 + 8] - Mb) / Sb;
            float ws0 = ts[tb0 + r0] * sc0;
            float ws1 = ts[tb0 + r0 + 8] * sc1;
            float b0v = g_buv[n0 + col], b1v = g_buv[n0 + col + 1];
            float2 x0 = *(const float2*)(x + (size_t)r * DIM_ + n0 + col);
            float2 x1 = *(const float2*)(x + (size_t)(r + 8) * DIM_ + n0 + col);
            *(float2*)(out + (size_t)r * DIM_ + n0 + col) =
                make_float2(sc0 * d[fm][fn][0] + x0.x + ws0 * b0v,
                            sc0 * d[fm][fn][1] + x0.y + ws0 * b1v);
            *(float2*)(out + (size_t)(r + 8) * DIM_ + n0 + col) =
                make_float2(sc1 * d[fm][fn][2] + x1.x + ws1 * b0v,
                            sc1 * d[fm][fn][3] + x1.y + ws1 * b1v); )
    }
}

// ---------------------------------------------------------------------------
// Launch: ONE kernel
// ---------------------------------------------------------------------------
extern "C" void kernel_launch(void* const* d_in, const int* in_sizes, int n_in,
                              void* d_out, int out_size)
{
    const float* x      = (const float*)d_in[0];
    const float* vision = (const float*)d_in[1];
    const int*   mask   = (const int*)  d_in[2];
    const float* Wu     = (const float*)d_in[3];
    const float* bu     = (const float*)d_in[4];
    const float* Wk     = (const float*)d_in[5];
    const float* Wv     = (const float*)d_in[6];

    static int init_done = 0;
    if (!init_done) {
        cudaFuncSetAttribute(mega_kernel,
                             cudaFuncAttributeMaxDynamicSharedMemorySize, DSM_BYTES);
        init_done = 1;
    }

    mega_kernel<<<NCTA, 256, DSM_BYTES>>>(x, vision, mask, Wu, bu, Wk, Wv, (float*)d_out);
}

// round 14
// speedup vs baseline: 1.8065x; 1.0881x over previous
#include <cuda_runtime.h>
#include <cuda_bf16.h>
#include <cstdint>
#include <math.h>

#define B_   4
#define T_   256
#define V_   1024
#define DIM_ 1024
#define CV_  256
#define NCTA 148

// ---------------------------------------------------------------------------
// Scratch (static device globals)
// ---------------------------------------------------------------------------
__device__ __nv_bfloat16 g_visb[B_ * V_ * CV_];   // vision bf16
__device__ __nv_bfloat16 g_Wuk [CV_ * DIM_];      // Wu@Wk bf16
__device__ __nv_bfloat16 g_Wuv [CV_ * DIM_];      // Wu@Wv bf16
__device__ float         g_part[8][CV_ * DIM_];   // split-K partials
__device__ float         g_buk [DIM_];
__device__ float         g_buv [DIM_];
__device__ unsigned      g_maskT [B_ * T_ * (V_ / 32)]; // bit-packed (b,t,v)
__device__ float         g_aggp[2][B_ * T_ * CV_];// flash V-half partial agg (fp32)
__device__ float2        g_msp [2][B_ * T_];      // flash V-half partial (m,s)
__device__ unsigned      g_bar_cnt;
__device__ unsigned      g_bar_gen;

// ---------------------------------------------------------------------------
// helpers
// ---------------------------------------------------------------------------
__device__ __forceinline__ uint32_t smem_u32(const void* p) {
    uint32_t a;
    asm("{ .reg .u64 t; cvta.to.shared.u64 t, %1; cvt.u32.u64 %0, t; }"
        : "=r"(a) : "l"(p));
    return a;
}
__device__ __forceinline__ void cp_async16(uint32_t dst, const void* src) {
    asm volatile("cp.async.cg.shared.global [%0], [%1], 16;" :: "r"(dst), "l"(src));
}
#define CP_COMMIT() asm volatile("cp.async.commit_group;" ::: "memory")
#define CP_WAIT(n)  asm volatile("cp.async.wait_group %0;" :: "n"(n) : "memory")

__device__ __forceinline__ void ldmatrix_x4(uint32_t* r, uint32_t addr) {
    asm volatile("ldmatrix.sync.aligned.m8n8.x4.shared.b16 {%0,%1,%2,%3}, [%4];"
                 : "=r"(r[0]), "=r"(r[1]), "=r"(r[2]), "=r"(r[3]) : "r"(addr));
}
__device__ __forceinline__ void ldmatrix_x4_trans(uint32_t* r, uint32_t addr) {
    asm volatile("ldmatrix.sync.aligned.m8n8.x4.trans.shared.b16 {%0,%1,%2,%3}, [%4];"
                 : "=r"(r[0]), "=r"(r[1]), "=r"(r[2]), "=r"(r[3]) : "r"(addr));
}
__device__ __forceinline__ void mma16816(float* d, const uint32_t* a, const uint32_t* b) {
    asm volatile(
        "mma.sync.aligned.m16n8k16.row.col.f32.bf16.bf16.f32 "
        "{%0,%1,%2,%3},{%4,%5,%6,%7},{%8,%9},{%0,%1,%2,%3};"
        : "+f"(d[0]), "+f"(d[1]), "+f"(d[2]), "+f"(d[3])
        : "r"(a[0]), "r"(a[1]), "r"(a[2]), "r"(a[3]), "r"(b[0]), "r"(b[1]));
}

// grid-wide barrier (all NCTA CTAs co-resident: 1 CTA/SM)
__device__ __forceinline__ void grid_sync() {
    __syncthreads();
    if (threadIdx.x == 0) {
        volatile unsigned* vgen = &g_bar_gen;
        unsigned gen = *vgen;
        __threadfence();
        if (atomicAdd(&g_bar_cnt, 1u) == NCTA - 1) {
            g_bar_cnt = 0u;
            __threadfence();
            *(volatile unsigned*)&g_bar_gen = gen + 1u;
        } else {
            while (*vgen == gen) { }
        }
        __threadfence();
    }
    __syncthreads();
}

__device__ __forceinline__ void ms_comb(float& m, float& s, float m2, float s2) {
    float nm = fmaxf(m, m2);
    s = s * __expf(m - nm) + s2 * __expf(m2 - nm);
    m = nm;
}
__device__ __forceinline__ void st_bf16x4(__nv_bfloat162* o, int i, float4 a) {
    o[2 * i]     = __floats2bfloat162_rn(a.x, a.y);
    o[2 * i + 1] = __floats2bfloat162_rn(a.z, a.w);
}
__device__ __forceinline__ void st_bf16x4_smem(void* p, float4 v) {
    __nv_bfloat162 h0 = __floats2bfloat162_rn(v.x, v.y);
    __nv_bfloat162 h1 = __floats2bfloat162_rn(v.z, v.w);
    uint2 u;
    u.x = *(uint32_t*)&h0;
    u.y = *(uint32_t*)&h1;
    *(uint2*)p = u;
}

// Flash smem layout
#define F_VIS_STRIDE 67584            // 128*264*2
#define F_OFF_Q      135168
#define F_OFF_P      143616
#define F_OFF_WRED   147968           // [16][8] f32
#define F_OFF_WRED2  148480           // [16][8] f32
#define F_OFF_BD     148992           // [16] f32
#define DSM_BYTES    149504

// P5 smem layout
#define P6_BS_OFF    67584
#define P6_ARR_OFF   102912

// ---------------------------------------------------------------------------
// tile_p1: C += A_f32[128,K] @ B_f32[K,128]  (convert-on-load, reg-staged)
// ---------------------------------------------------------------------------
__device__ __forceinline__ void tile_p1(const float* __restrict__ A, int lda,
                                        const float* __restrict__ Bm, int ldb,
                                        int nchunks, char* dsm, float d[2][8][4]) {
    const int tid = threadIdx.x, lane = tid & 31, wid = tid >> 5;
    const int warpM = wid & 3, warpN = wid >> 2;
    __nv_bfloat16* As = (__nv_bfloat16*)dsm;             // [128][72]
    __nv_bfloat16* Bs = (__nv_bfloat16*)(dsm + 18432);   // [64][136]
    #pragma unroll
    for (int i = 0; i < 2; i++)
        #pragma unroll
        for (int j = 0; j < 8; j++)
            #pragma unroll
            for (int q = 0; q < 4; q++) d[i][j][q] = 0.0f;

    float4 ar[8], br[8];
    auto ldA = [&](int c) {
        #pragma unroll
        for (int h = 0; h < 8; h++) {
            int i = h * 256 + tid, row = i >> 4, pc = i & 15;
            ar[h] = *(const float4*)(A + (size_t)row * lda + c * 64 + pc * 4);
        }
    };
    auto ldB = [&](int c) {
        #pragma unroll
        for (int h = 0; h < 8; h++) {
            int i = h * 256 + tid, row = i >> 5, pc = i & 31;
            br[h] = *(const float4*)(Bm + (size_t)(c * 64 + row) * ldb + pc * 4);
        }
    };
    ldA(0); ldB(0);
    for (int c = 0; c < nchunks; c++) {
        __syncthreads();
        #pragma unroll
        for (int h = 0; h < 8; h++) {
            int i = h * 256 + tid, row = i >> 4, pc = i & 15;
            st_bf16x4_smem(As + row * 72 + pc * 4, ar[h]);
        }
        #pragma unroll
        for (int h = 0; h < 8; h++) {
            int i = h * 256 + tid, row = i >> 5, pc = i & 31;
            st_bf16x4_smem(Bs + row * 136 + pc * 4, br[h]);
        }
        if (c + 1 < nchunks) { ldA(c + 1); ldB(c + 1); }
        __syncthreads();
        #pragma unroll
        for (int ks = 0; ks < 4; ks++) {
            uint32_t a[2][4];
            #pragma unroll
            for (int fm = 0; fm < 2; fm++) {
                int r  = warpM * 32 + fm * 16 + (lane & 7) + ((lane >> 3) & 1) * 8;
                int kk = ks * 16 + (lane >> 4) * 8;
                ldmatrix_x4(a[fm], smem_u32(As + r * 72 + kk));
            }
            uint32_t b[8][2];
            #pragma unroll
            for (int i = 0; i < 4; i++) {
                int kk = ks * 16 + (lane & 15);
                int nn = warpN * 64 + i * 16 + (lane >> 4) * 8;
                uint32_t tmp[4];
                ldmatrix_x4_trans(tmp, smem_u32(Bs + kk * 136 + nn));
                b[2*i][0]   = tmp[0]; b[2*i][1]   = tmp[1];
                b[2*i+1][0] = tmp[2]; b[2*i+1][1] = tmp[3];
            }
            #pragma unroll
            for (int fm = 0; fm < 2; fm++)
                #pragma unroll
                for (int fn = 0; fn < 8; fn++)
                    mma16816(d[fm][fn], a[fm], b[fn]);
        }
    }
    __syncthreads();
}

// ---------------------------------------------------------------------------
// tile_p3: C += A_f32[128,K] @ B_bf16[128,K]^T (A convert-on-load, B reg-staged)
// ---------------------------------------------------------------------------
__device__ __forceinline__ void tile_p3(const float* __restrict__ A, int lda,
                                        const __nv_bfloat16* __restrict__ Bm, int ldb,
                                        int nchunks, char* dsm, float d[2][8][4]) {
    const int tid = threadIdx.x, lane = tid & 31, wid = tid >> 5;
    const int warpM = wid & 3, warpN = wid >> 2;
    __nv_bfloat16* As = (__nv_bfloat16*)dsm;             // [128][72]
    __nv_bfloat16* Bs = (__nv_bfloat16*)(dsm + 18432);   // [128][72]
    #pragma unroll
    for (int i = 0; i < 2; i++)
        #pragma unroll
        for (int j = 0; j < 8; j++)
            #pragma unroll
            for (int q = 0; q < 4; q++) d[i][j][q] = 0.0f;

    float4 ar[8];
    uint4 br4[4];
    auto ldA = [&](int c) {
        #pragma unroll
        for (int h = 0; h < 8; h++) {
            int i = h * 256 + tid, row = i >> 4, pc = i & 15;
            ar[h] = *(const float4*)(A + (size_t)row * lda + c * 64 + pc * 4);
        }
    };
    auto ldB = [&](int c) {
        #pragma unroll
        for (int h = 0; h < 4; h++) {
            int i = h * 256 + tid, row = i >> 3, pc = i & 7;
            br4[h] = *(const uint4*)(Bm + (size_t)row * ldb + c * 64 + pc * 8);
        }
    };
    ldA(0); ldB(0);
    for (int c = 0; c < nchunks; c++) {
        __syncthreads();
        #pragma unroll
        for (int h = 0; h < 8; h++) {
            int i = h * 256 + tid, row = i >> 4, pc = i & 15;
            st_bf16x4_smem(As + row * 72 + pc * 4, ar[h]);
        }
        #pragma unroll
        for (int h = 0; h < 4; h++) {
            int i = h * 256 + tid, row = i >> 3, pc = i & 7;
            *(uint4*)(Bs + row * 72 + pc * 8) = br4[h];
        }
        if (c + 1 < nchunks) { ldA(c + 1); ldB(c + 1); }
        __syncthreads();
        #pragma unroll
        for (int ks = 0; ks < 4; ks++) {
            uint32_t a[2][4];
            #pragma unroll
            for (int fm = 0; fm < 2; fm++) {
                int r  = warpM * 32 + fm * 16 + (lane & 7) + ((lane >> 3) & 1) * 8;
                int kk = ks * 16 + (lane >> 4) * 8;
                ldmatrix_x4(a[fm], smem_u32(As + r * 72 + kk));
            }
            uint32_t b[8][2];
            #pragma unroll
            for (int i = 0; i < 4; i++) {
                int r  = warpN * 64 + i * 16 + (lane & 7) + (lane >> 4) * 8;
                int kk = ks * 16 + ((lane >> 3) & 1) * 8;
                uint32_t tmp[4];
                ldmatrix_x4(tmp, smem_u32(Bs + r * 72 + kk));
                b[2*i][0]   = tmp[0]; b[2*i][1]   = tmp[1];
                b[2*i+1][0] = tmp[2]; b[2*i+1][1] = tmp[3];
            }
            #pragma unroll
            for (int fm = 0; fm < 2; fm++)
                #pragma unroll
                for (int fn = 0; fn < 8; fn++)
                    mma16816(d[fm][fn], a[fm], b[fn]);
        }
    }
    __syncthreads();
}

#define FRAG_LOOP(...) \
    { const int lane_ = threadIdx.x & 31, wid_ = threadIdx.x >> 5; \
      const int warpM_ = wid_ & 3, warpN_ = wid_ >> 2; \
      _Pragma("unroll") for (int fm = 0; fm < 2; fm++) \
      _Pragma("unroll") for (int fn = 0; fn < 8; fn++) { \
          int r0  = warpM_ * 32 + fm * 16 + (lane_ >> 2); \
          int col = warpN_ * 64 + fn * 8 + 2 * (lane_ & 3); \
          __VA_ARGS__ } }

// ---------------------------------------------------------------------------
// The persistent mega-kernel
// ---------------------------------------------------------------------------
extern "C" __global__ void __launch_bounds__(256)
mega_kernel(const float* __restrict__ x, const float* __restrict__ vision,
            const int* __restrict__ mask, const float* __restrict__ Wu,
            const float* __restrict__ bu, const float* __restrict__ Wk,
            const float* __restrict__ Wv, float* __restrict__ out)
{
    extern __shared__ char dsm[];
    const int cta = blockIdx.x, tid = threadIdx.x;
    const int lane = tid & 31, wid = tid >> 5;

    // ============ P0||P1 merged ============
    if (cta < 64) {
        // Wuk/Wuv = Wu @ Wk/Wv, split-K=2 (64 jobs, K=512 each)
        int kv = cta & 1, split = (cta >> 1) & 1, mt = (cta >> 2) & 1, nt = cta >> 3;
        int kbase = split * 512, m0 = mt * 128, n0 = nt * 128;
        const float* A = Wu + (size_t)m0 * DIM_ + kbase;
        const float* Bm = (kv ? Wv : Wk) + (size_t)kbase * DIM_ + n0;
        float d[2][8][4];
        tile_p1(A, DIM_, Bm, DIM_, 8, dsm, d);
        float* Cp = g_part[kv * 2 + split];
        FRAG_LOOP(
            *(float2*)(Cp + (size_t)(m0 + r0) * DIM_ + n0 + col)     = make_float2(d[fm][fn][0], d[fm][fn][1]);
            *(float2*)(Cp + (size_t)(m0 + r0 + 8) * DIM_ + n0 + col) = make_float2(d[fm][fn][2], d[fm][fn][3]); )
    } else {
        const int idx = cta - 64;                 // 0..83
        // vision convert (strided over 84 CTAs)
        for (int i = idx * 256 + tid; i < B_*V_*CV_/4; i += 84 * 256) {
            float4 v = ((const float4*)vision)[i];
            st_bf16x4((__nv_bfloat162*)g_visb, i, v);
        }
        // maskT bitpack: 128 jobs strided over 84 CTAs
        int* tile = (int*)dsm;   // [32][257]
        for (int job = idx; job < 128; job += 84) {
            int b = job >> 5, v0 = (job & 31) * 32;
            const int* mp = mask + (size_t)b * V_ * T_;
            __syncthreads();
            #pragma unroll
            for (int vr = 0; vr < 32; vr++)
                tile[vr * 257 + tid] = mp[(size_t)(v0 + vr) * T_ + tid];
            __syncthreads();
            unsigned word = 0;
            #pragma unroll
            for (int vr = 0; vr < 32; vr++)
                word |= (tile[vr * 257 + tid] != 0 ? 1u : 0u) << vr;
            g_maskT[((size_t)b * T_ + tid) * 32 + (job & 31)] = word;
        }
        __syncthreads();
        // bias fold: 32 jobs on idx<32 CTAs
        if (idx < 32) {
            int kv = idx & 1, n0b = (idx >> 1) * 64;
            const float* W = kv ? Wv : Wk;
            int tx = tid & 63, ty = tid >> 6;
            float acc = 0.0f;
            int c0 = ty * 256;
            #pragma unroll 8
            for (int c = c0; c < c0 + 256; c++)
                acc = fmaf(bu[c], W[(size_t)c * DIM_ + n0b + tx], acc);
            float* sp = (float*)dsm;
            sp[ty * 64 + tx] = acc;
            __syncthreads();
            if (ty == 0)
                (kv ? g_buv : g_buk)[n0b + tx] = sp[tx] + sp[64+tx] + sp[128+tx] + sp[192+tx];
        }
    }
    grid_sync();

    // ============ P2: reduce Wuk/Wuv -> bf16 (2 partials) ============
    for (int i = cta * 256 + tid; i < 131072; i += NCTA * 256) {
        int kv = i >> 16, j = i & 65535;
        float4 p0 = ((const float4*)g_part[kv * 2])[j];
        float4 p1 = ((const float4*)g_part[kv * 2 + 1])[j];
        float4 a = make_float4(p0.x + p1.x, p0.y + p1.y, p0.z + p1.z, p0.w + p1.w);
        st_bf16x4((__nv_bfloat162*)(kv ? g_Wuv : g_Wuk), j, a);
    }
    grid_sync();

    // ============ P3: xq = x @ Wuk^T, split-K=8, fp32 A (128 jobs) ============
    if (cta < 128) {
        int split = cta & 7, mt = (cta >> 3) & 7, nt = cta >> 6;
        int kbase = split * 128, m0 = mt * 128, n0 = nt * 128;
        const float* A = x + (size_t)m0 * DIM_ + kbase;
        const __nv_bfloat16* Bm = g_Wuk + (size_t)n0 * DIM_ + kbase;
        float d[2][8][4];
        tile_p3(A, DIM_, Bm, DIM_, 2, dsm, d);
        float* Cp = g_part[split];
        FRAG_LOOP(
            *(float2*)(Cp + (size_t)(m0 + r0) * CV_ + n0 + col)     = make_float2(d[fm][fn][0], d[fm][fn][1]);
            *(float2*)(Cp + (size_t)(m0 + r0 + 8) * CV_ + n0 + col) = make_float2(d[fm][fn][2], d[fm][fn][3]); )
    }
    grid_sync();

    // ============ P4: FLASH — V-split x2, 128 CTAs, reg-replicated (m,s) ============
    if (cta < 128) {
        const int half = cta >> 6, rem = cta & 63;
        const int b = rem >> 4, t0 = (rem & 15) * 16;
        char* Qs = dsm + F_OFF_Q;
        char* Ps = dsm + F_OFF_P;
        float* wred  = (float*)(dsm + F_OFF_WRED);    // [16][8] chunk maxima
        float* wred2 = (float*)(dsm + F_OFF_WRED2);   // [16][8] chunk sums
        float* bd    = (float*)(dsm + F_OFF_BD);      // [16]
        const int w8 = wid;
        const int r_lo = lane >> 2, r_hi = r_lo + 8;
        const int vrow0 = b * V_ + half * 512;
        const int vbit0 = half * 512;

        #pragma unroll
        for (int h = 0; h < 16; h++) {
            int p = h * 256 + tid; int row = p >> 5, pc = p & 31;
            cp_async16(smem_u32(dsm + (row * 264 + pc * 8) * 2),
                       g_visb + ((size_t)(vrow0 + row)) * CV_ + pc * 8);
        }
        CP_COMMIT();

        // Q tile: reduce 16x256 from the 8 xq split partials -> bf16 smem
        #pragma unroll
        for (int h = 0; h < 16; h++) {
            int i = h * 256 + tid;
            int row = i >> 8, cc = i & 255;
            float acc = 0.0f;
            #pragma unroll
            for (int s = 0; s < 8; s++)
                acc += g_part[s][((size_t)(b * T_ + t0 + row) << 8) + cc];
            *(__nv_bfloat16*)(Qs + (row * 264 + cc) * 2) = __float2bfloat16(acc);
        }
        // bdot: warp w -> tokens 2w, 2w+1
        {
            int tk = wid * 2;
            #pragma unroll
            for (int u = 0; u < 2; u++) {
                const float* xr = x + ((size_t)(b * T_ + t0 + tk + u)) * DIM_;
                float acc = 0.0f;
                #pragma unroll
                for (int k = 0; k < 32; k++)
                    acc = fmaf(xr[k * 32 + lane], g_buk[k * 32 + lane], acc);
                #pragma unroll
                for (int off = 16; off > 0; off >>= 1)
                    acc += __shfl_down_sync(0xffffffffu, acc, off);
                if (lane == 0) bd[tk + u] = acc;
            }
        }
        __syncthreads();
        const float bd_lo = bd[r_lo], bd_hi = bd[r_hi];

        // per-thread replicated online state for my two rows
        float m_lo = -1e30f, s_lo = 0.0f, m_hi = -1e30f, s_hi = 0.0f;

        float d2[4][4];
        #pragma unroll
        for (int i = 0; i < 4; i++)
            #pragma unroll
            for (int q = 0; q < 4; q++) d2[i][q] = 0.0f;

        for (int c = 0; c < 4; c++) {
            int buf = c & 1;
            if (c + 1 < 4) {
                int nbuf = (c + 1) & 1;
                #pragma unroll
                for (int h = 0; h < 16; h++) {
                    int p = h * 256 + tid; int row = p >> 5, pc = p & 31;
                    cp_async16(smem_u32(dsm + nbuf * F_VIS_STRIDE + (row * 264 + pc * 8) * 2),
                               g_visb + ((size_t)(vrow0 + (c + 1) * 128 + row)) * CV_ + pc * 8);
                }
                CP_COMMIT(); CP_WAIT(1);
            } else CP_WAIT(0);
            __syncthreads();                       // sync0: VIS ready, wred readable
            char* VIS = dsm + buf * F_VIS_STRIDE;

            // --- mma1: logits tile [16 x 128] ---
            float d1[2][4];
            #pragma unroll
            for (int i = 0; i < 2; i++)
                #pragma unroll
                for (int q = 0; q < 4; q++) d1[i][q] = 0.0f;
            #pragma unroll
            for (int ks = 0; ks < 16; ks++) {
                uint32_t aF[4];
                int rA = lane & 15, kk = ks * 16 + (lane >> 4) * 8;
                ldmatrix_x4(aF, smem_u32(Qs + (rA * 264 + kk) * 2));
                int rb = w8 * 16 + (lane & 7) + (lane >> 4) * 8;
                int kkb = ks * 16 + ((lane >> 3) & 1) * 8;
                uint32_t t4[4];
                ldmatrix_x4(t4, smem_u32(VIS + (rb * 264 + kkb) * 2));
                uint32_t b0[2] = {t4[0], t4[1]}, b1[2] = {t4[2], t4[3]};
                mma16816(d1[0], aF, b0);
                mma16816(d1[1], aF, b1);
            }

            // --- masked online softmax (register-replicated) ---
            int v0 = vbit0 + c * 128;
            unsigned wlo = g_maskT[((size_t)(b * T_ + t0 + r_lo)) * 32 + ((v0 + w8 * 16) >> 5)];
            unsigned whi = g_maskT[((size_t)(b * T_ + t0 + r_hi)) * 32 + ((v0 + w8 * 16) >> 5)];
            float lv[2][4]; bool mk[2][4];
            float mx0 = -1e30f, mx1 = -1e30f;
            #pragma unroll
            for (int fn = 0; fn < 2; fn++) {
                int cb = w8 * 16 + fn * 8 + 2 * (lane & 3);
                #pragma unroll
                for (int j = 0; j < 4; j++) {
                    int cc = cb + (j & 1);
                    bool hi = (j >> 1);
                    unsigned word = hi ? whi : wlo;
                    bool m = (word >> (cc & 31)) & 1u;
                    float l = (d1[fn][j] + (hi ? bd_hi : bd_lo)) * 0.03125f;
                    lv[fn][j] = l; mk[fn][j] = m;
                    if (m) { if (hi) mx1 = fmaxf(mx1, l); else mx0 = fmaxf(mx0, l); }
                }
            }
            #pragma unroll
            for (int off = 1; off <= 2; off <<= 1) {
                mx0 = fmaxf(mx0, __shfl_xor_sync(0xffffffffu, mx0, off));
                mx1 = fmaxf(mx1, __shfl_xor_sync(0xffffffffu, mx1, off));
            }
            if ((lane & 3) == 0) { wred[r_lo * 8 + w8] = mx0; wred[r_hi * 8 + w8] = mx1; }
            __syncthreads();                       // syncA: maxima published
            float tm_lo = wred[r_lo * 8], tm_hi = wred[r_hi * 8];
            #pragma unroll
            for (int k = 1; k < 8; k++) {
                tm_lo = fmaxf(tm_lo, wred[r_lo * 8 + k]);
                tm_hi = fmaxf(tm_hi, wred[r_hi * 8 + k]);
            }
            float mn_lo = fmaxf(m_lo, tm_lo), mn_hi = fmaxf(m_hi, tm_hi);
            float f_lo = __expf(m_lo - mn_lo), f_hi = __expf(m_hi - mn_hi);
            m_lo = mn_lo; m_hi = mn_hi;

            float se0 = 0.0f, se1 = 0.0f;
            #pragma unroll
            for (int fn = 0; fn < 2; fn++) {
                int cb = w8 * 16 + fn * 8 + 2 * (lane & 3);
                float p0 = mk[fn][0] ? __expf(lv[fn][0] - m_lo) : 0.0f;
                float p1 = mk[fn][1] ? __expf(lv[fn][1] - m_lo) : 0.0f;
                float p2 = mk[fn][2] ? __expf(lv[fn][2] - m_hi) : 0.0f;
                float p3 = mk[fn][3] ? __expf(lv[fn][3] - m_hi) : 0.0f;
                se0 += p0 + p1; se1 += p2 + p3;
                *(__nv_bfloat162*)(Ps + (r_lo * 136 + cb) * 2) = __floats2bfloat162_rn(p0, p1);
                *(__nv_bfloat162*)(Ps + (r_hi * 136 + cb) * 2) = __floats2bfloat162_rn(p2, p3);
            }
            #pragma unroll
            for (int off = 1; off <= 2; off <<= 1) {
                se0 += __shfl_xor_sync(0xffffffffu, se0, off);
                se1 += __shfl_xor_sync(0xffffffffu, se1, off);
            }
            if ((lane & 3) == 0) { wred2[r_lo * 8 + w8] = se0; wred2[r_hi * 8 + w8] = se1; }
            // rescale accumulator by my rows' factors
            #pragma unroll
            for (int fn = 0; fn < 4; fn++) {
                d2[fn][0] *= f_lo; d2[fn][1] *= f_lo;
                d2[fn][2] *= f_hi; d2[fn][3] *= f_hi;
            }
            __syncthreads();                       // syncB: Ps + sums published
            {
                float ss0 = 0.0f, ss1 = 0.0f;
                #pragma unroll
                for (int k = 0; k < 8; k++) {
                    ss0 += wred2[r_lo * 8 + k];
                    ss1 += wred2[r_hi * 8 + k];
                }
                s_lo = s_lo * f_lo + ss0;
                s_hi = s_hi * f_hi + ss1;
            }

            // --- mma2: acc += P @ Vis ---
            #pragma unroll
            for (int ks = 0; ks < 8; ks++) {
                uint32_t aF[4];
                int rA = lane & 15, kk = ks * 16 + (lane >> 4) * 8;
                ldmatrix_x4(aF, smem_u32(Ps + (rA * 136 + kk) * 2));
                #pragma unroll
                for (int i = 0; i < 2; i++) {
                    int kkb = ks * 16 + (lane & 15);
                    int nn = w8 * 32 + i * 16 + (lane >> 4) * 8;
                    uint32_t t4[4];
                    ldmatrix_x4_trans(t4, smem_u32(VIS + (kkb * 264 + nn) * 2));
                    uint32_t b0[2] = {t4[0], t4[1]}, b1[2] = {t4[2], t4[3]};
                    mma16816(d2[2*i], aF, b0);
                    mma16816(d2[2*i+1], aF, b1);
                }
            }
        }
        float* AP = g_aggp[half];
        #pragma unroll
        for (int fn = 0; fn < 4; fn++) {
            int cb = w8 * 32 + fn * 8 + 2 * (lane & 3);
            *(float2*)(AP + ((size_t)(b * T_ + t0 + r_lo)) * CV_ + cb) =
                make_float2(d2[fn][0], d2[fn][1]);
            *(float2*)(AP + ((size_t)(b * T_ + t0 + r_hi)) * CV_ + cb) =
                make_float2(d2[fn][2], d2[fn][3]);
        }
        if (w8 == 0 && (lane & 3) == 0) {
            g_msp[half][b * T_ + t0 + r_lo] = make_float2(m_lo, s_lo);
            g_msp[half][b * T_ + t0 + r_hi] = make_float2(m_hi, s_hi);
        }
    }
    grid_sync();

    // ============ P5: out = x + scale*((merged agg) @ Wuv) + wsum*buv (64 jobs) ============
    if (cta < 64) {
        const int mt = cta >> 3, nt = cta & 7;
        const int m0 = mt * 128, n0 = nt * 128, b = mt >> 1;
        const int tb0 = (mt & 1) * 128;
        const int warpM = wid & 3, warpN = wid >> 2;

        __nv_bfloat16* As = (__nv_bfloat16*)dsm;         // [128][264]
        char* BsBase = dsm + P6_BS_OFF;                  // 2 x [64][136]
        float* tm  = (float*)(dsm + P6_ARR_OFF);
        float* ts  = tm + 256;
        float* fa0 = ts + 256;
        float* fa1 = fa0 + 256;
        float* rm  = fa1 + 256;
        float* rs  = rm + 256;

        #pragma unroll
        for (int h = 0; h < 4; h++) {
            int i = h * 256 + tid, row = i >> 4, pc = i & 15;
            cp_async16(smem_u32(BsBase + (row * 136 + pc * 8) * 2),
                       g_Wuv + (size_t)row * DIM_ + n0 + pc * 8);
        }
        CP_COMMIT();

        {
            float2 p0 = g_msp[0][b * T_ + tid], p1 = g_msp[1][b * T_ + tid];
            float mmv = fmaxf(p0.x, p1.x);
            float f0 = __expf(p0.x - mmv), f1 = __expf(p1.x - mmv);
            tm[tid] = mmv; ts[tid] = p0.y * f0 + p1.y * f1;
            fa0[tid] = f0; fa1[tid] = f1;
        }
        __syncthreads();
        rm[tid] = tm[tid]; rs[tid] = ts[tid];
        __syncthreads();
        for (int st = 128; st > 0; st >>= 1) {
            if (tid < st) {
                float mmv = rm[tid], ssv = rs[tid];
                ms_comb(mmv, ssv, rm[tid + st], rs[tid + st]);
                rm[tid] = mmv; rs[tid] = ssv;
            }
            __syncthreads();
        }
        const float Mb = rm[0], Sb = rs[0];

        for (int i = tid; i < 128 * 64; i += 256) {
            int row = i >> 6, pc = i & 63;
            float4 a0 = *(const float4*)(g_aggp[0] + ((size_t)(m0 + row)) * CV_ + pc * 4);
            float4 a1 = *(const float4*)(g_aggp[1] + ((size_t)(m0 + row)) * CV_ + pc * 4);
            float f0 = fa0[tb0 + row], f1 = fa1[tb0 + row];
            float4 mg = make_float4(a0.x * f0 + a1.x * f1, a0.y * f0 + a1.y * f1,
                                    a0.z * f0 + a1.z * f1, a0.w * f0 + a1.w * f1);
            st_bf16x4_smem(As + row * 264 + pc * 4, mg);
        }
        __syncthreads();

        float d[2][8][4];
        #pragma unroll
        for (int i = 0; i < 2; i++)
            #pragma unroll
            for (int j = 0; j < 8; j++)
                #pragma unroll
                for (int q = 0; q < 4; q++) d[i][j][q] = 0.0f;

        for (int c = 0; c < 4; c++) {
            int buf = c & 1;
            if (c + 1 < 4) {
                int nbuf = (c + 1) & 1;
                #pragma unroll
                for (int h = 0; h < 4; h++) {
                    int i = h * 256 + tid, row = i >> 4, pc = i & 15;
                    cp_async16(smem_u32(BsBase + nbuf * 17408 + (row * 136 + pc * 8) * 2),
                               g_Wuv + (size_t)((c + 1) * 64 + row) * DIM_ + n0 + pc * 8);
                }
                CP_COMMIT(); CP_WAIT(1);
            } else CP_WAIT(0);
            __syncthreads();
            __nv_bfloat16* Bs = (__nv_bfloat16*)(BsBase + buf * 17408);
            #pragma unroll
            for (int ks = 0; ks < 4; ks++) {
                uint32_t a[2][4];
                #pragma unroll
                for (int fm = 0; fm < 2; fm++) {
                    int r  = warpM * 32 + fm * 16 + (lane & 7) + ((lane >> 3) & 1) * 8;
                    int kk = c * 64 + ks * 16 + (lane >> 4) * 8;
                    ldmatrix_x4(a[fm], smem_u32(As + r * 264 + kk));
                }
                uint32_t bfr[8][2];
                #pragma unroll
                for (int i = 0; i < 4; i++) {
                    int kk = ks * 16 + (lane & 15);
                    int nn = warpN * 64 + i * 16 + (lane >> 4) * 8;
                    uint32_t tmp[4];
                    ldmatrix_x4_trans(tmp, smem_u32(Bs + kk * 136 + nn));
                    bfr[2*i][0]   = tmp[0]; bfr[2*i][1]   = tmp[1];
                    bfr[2*i+1][0] = tmp[2]; bfr[2*i+1][1] = tmp[3];
                }
                #pragma unroll
                for (int fm = 0; fm < 2; fm++)
                    #pragma unroll
                    for (int fn = 0; fn < 8; fn++)
                        mma16816(d[fm][fn], a[fm], bfr[fn]);
            }
            __syncthreads();
        }

        FRAG_LOOP(
            int r = m0 + r0;
            float sc0 = __expf(tm[tb0 + r0] - Mb) / Sb;
            float sc1 = __expf(tm[tb0 + r0 + 8] - Mb) / Sb;
            float ws0 = ts[tb0 + r0] * sc0;
            float ws1 = ts[tb0 + r0 + 8] * sc1;
            float b0v = g_buv[n0 + col], b1v = g_buv[n0 + col + 1];
            float2 x0 = *(const float2*)(x + (size_t)r * DIM_ + n0 + col);
            float2 x1 = *(const float2*)(x + (size_t)(r + 8) * DIM_ + n0 + col);
            *(float2*)(out + (size_t)r * DIM_ + n0 + col) =
                make_float2(sc0 * d[fm][fn][0] + x0.x + ws0 * b0v,
                            sc0 * d[fm][fn][1] + x0.y + ws0 * b1v);
            *(float2*)(out + (size_t)(r + 8) * DIM_ + n0 + col) =
                make_float2(sc1 * d[fm][fn][2] + x1.x + ws1 * b0v,
                            sc1 * d[fm][fn][3] + x1.y + ws1 * b1v); )
    }
}

// ---------------------------------------------------------------------------
// Launch: ONE kernel
// ---------------------------------------------------------------------------
extern "C" void kernel_launch(void* const* d_in, const int* in_sizes, int n_in,
                              void* d_out, int out_size)
{
    const float* x      = (const float*)d_in[0];
    const float* vision = (const float*)d_in[1];
    const int*   mask   = (const int*)  d_in[2];
    const float* Wu     = (const float*)d_in[3];
    const float* bu     = (const float*)d_in[4];
    const float* Wk     = (const float*)d_in[5];
    const float* Wv     = (const float*)d_in[6];

    static int init_done = 0;
    if (!init_done) {
        cudaFuncSetAttribute(mega_kernel,
                             cudaFuncAttributeMaxDynamicSharedMemorySize, DSM_BYTES);
        init_done = 1;
    }

    mega_kernel<<<NCTA, 256, DSM_BYTES>>>(x, vision, mask, Wu, bu, Wk, Wv, (float*)d_out);
}